// round 11
// baseline (speedup 1.0000x reference)
#include <cuda_runtime.h>
#include <cuda_fp16.h>
#include <math.h>
#include <stdint.h>

// ---------------------------------------------------------------------------
// Swin3D block, fp16 mma.sync throughout.
// R10/R11: proj+AdaLN1 and FC2+AdaLN2 fused into full-row GEMM blocks (BN=512),
// eliminating the two adaln kernels and the g_pro/g_h2 fp32 round-trips.
// (Resubmit of R10 — infra failure, kernel never ran.)
// ---------------------------------------------------------------------------

#define L_TOK   36864
#define DMODEL  512
#define QKVDIM  1536
#define FFNDIM  2048
#define NWIN    256
#define WTOK    144
#define NHEAD   16
#define HDIM    32

typedef __half fp16;

// ---------------- scratch ---------------------------------------------------
__device__ fp16  g_xw  [L_TOK * DMODEL];
__device__ fp16  g_qkv [L_TOK * QKVDIM];   // attention-tile layout
__device__ fp16  g_aw  [L_TOK * DMODEL];
__device__ float g_x1  [L_TOK * DMODEL];
__device__ fp16  g_x1f [L_TOK * DMODEL];
__device__ fp16  g_h   [L_TOK * FFNDIM];
__device__ float g_mod [2048];

__device__ fp16 g_wqkv [QKVDIM * DMODEL];
__device__ fp16 g_wproj[DMODEL * DMODEL];
__device__ fp16 g_wfc1 [FFNDIM * DMODEL];
__device__ fp16 g_wfc2 [DMODEL * FFNDIM];

#define TILE_BYTES 9216

// ---------------- helpers ---------------------------------------------------
__device__ __forceinline__ uint32_t smem_u32(const void* p) {
    uint32_t a;
    asm("{ .reg .u64 t; cvta.to.shared.u64 t, %1; cvt.u32.u64 %0, t; }" : "=r"(a) : "l"(p));
    return a;
}
__device__ __forceinline__ uint32_t packh(float a, float b) {
    uint32_t r;
    asm("cvt.rn.f16x2.f32 %0, %1, %2;" : "=r"(r) : "f"(b), "f"(a));
    return r;
}
__device__ __forceinline__ void cpa16(uint32_t dst, const void* src) {
    asm volatile("cp.async.cg.shared.global [%0], [%1], 16;" :: "r"(dst), "l"(src) : "memory");
}
__device__ __forceinline__ void cp_commit() {
    asm volatile("cp.async.commit_group;" ::: "memory");
}
template<int N>
__device__ __forceinline__ void cp_wait() {
    asm volatile("cp.async.wait_group %0;" :: "n"(N) : "memory");
}
__device__ __forceinline__ void ldm4(uint32_t* r, uint32_t addr) {
    asm volatile("ldmatrix.sync.aligned.m8n8.x4.shared.b16 {%0,%1,%2,%3}, [%4];"
                 : "=r"(r[0]), "=r"(r[1]), "=r"(r[2]), "=r"(r[3]) : "r"(addr));
}
__device__ __forceinline__ void ldm4t(uint32_t* r, uint32_t addr) {
    asm volatile("ldmatrix.sync.aligned.m8n8.x4.trans.shared.b16 {%0,%1,%2,%3}, [%4];"
                 : "=r"(r[0]), "=r"(r[1]), "=r"(r[2]), "=r"(r[3]) : "r"(addr));
}
__device__ __forceinline__ void mma16816(float* d, const uint32_t* a,
                                         uint32_t b0, uint32_t b1) {
    asm volatile(
        "mma.sync.aligned.m16n8k16.row.col.f32.f16.f16.f32 "
        "{%0,%1,%2,%3},{%4,%5,%6,%7},{%8,%9},{%0,%1,%2,%3};"
        : "+f"(d[0]), "+f"(d[1]), "+f"(d[2]), "+f"(d[3])
        : "r"(a[0]), "r"(a[1]), "r"(a[2]), "r"(a[3]), "r"(b0), "r"(b1));
}
__device__ __forceinline__ uint32_t tsw(int n, int d) {
    return (uint32_t)(n * 64 + (((d >> 3) ^ (n & 3)) << 4) + (d & 7) * 2);
}
// window row -> spatial token row (shared by partition & fused-LN gather)
__device__ __forceinline__ int winrow_to_tok(int row) {
    int win = row / WTOK, n = row % WTOK;
    int wb = win & 7, hb = (win >> 3) & 15, cb = win >> 7;
    int i = n / 72, rem = n % 72, j = rem / 12, k = rem % 12;
    int cs = cb * 2 + i, hs = hb * 6 + j, ws = wb * 12 + k;
    int c0 = (cs + 1) & 3;
    int h0 = hs + 3;  if (h0 >= 96) h0 -= 96;
    int w0 = ws + 6;  if (w0 >= 96) w0 -= 96;
    return (c0 * 96 + h0) * 96 + w0;
}

// ---------------- weight transpose + fp16 ------------------------------------
__global__ void wconv_kernel(const float* __restrict__ w,
                             fp16* __restrict__ oh, int K, int N)
{
    __shared__ float t[32][33];
    int n0 = blockIdx.x * 32, k0 = blockIdx.y * 32;
    int tx = threadIdx.x, ty = threadIdx.y;
    for (int i = ty; i < 32; i += 8)
        t[i][tx] = w[(size_t)(k0 + i) * N + n0 + tx];
    __syncthreads();
    for (int i = ty; i < 32; i += 8)
        oh[(size_t)(n0 + i) * K + k0 + tx] = __float2half(t[tx][i]);
}

// ---------------- mma.sync fp16 GEMM (128x128 tile, 4-stage) -----------------
// OUTMODE: 1 = fp16 Ch, 2 = qkv attention tiles
#define GST 16384u
#define GOB 8192u

template<bool GELU, int OUTMODE>
__global__ __launch_bounds__(256)
void gemm_mma(const fp16* __restrict__ A, const fp16* __restrict__ B,
              const float* __restrict__ bias, fp16* __restrict__ Ch,
              int M, int N, int K)
{
    extern __shared__ char smc[];
    uint32_t sb = smem_u32(smc);
    int tid = threadIdx.x, wid = tid >> 5, lane = tid & 31;
    int wm = wid & 1, wn = wid >> 1;
    int bm = blockIdx.y * 128, bn = blockIdx.x * 128;

    int id0 = tid * 2;
    int row = id0 >> 2, c0 = id0 & 3;
    uint32_t doff[2]; int soff[2];
    #pragma unroll
    for (int l = 0; l < 2; l++) {
        int c = c0 + l;
        doff[l] = (uint32_t)(row * 64 + ((c ^ (row & 3)) << 4));
        soff[l] = c * 8;
    }
    const fp16* pA = A + (size_t)(bm + row) * K;
    const fp16* pB = B + (size_t)(bn + row) * K;

    float acc[4][4][4];
    #pragma unroll
    for (int i = 0; i < 4; i++)
        #pragma unroll
        for (int j = 0; j < 4; j++)
            #pragma unroll
            for (int q = 0; q < 4; q++) acc[i][j][q] = 0.0f;

    int NC = K >> 5;
    #pragma unroll
    for (int s = 0; s < 3; s++) {
        if (s < NC) {
            uint32_t base = sb + s * GST;
            int kof = s * 32;
            #pragma unroll
            for (int l = 0; l < 2; l++) {
                cpa16(base + doff[l],       pA + kof + soff[l]);
                cpa16(base + GOB + doff[l], pB + kof + soff[l]);
            }
        }
        cp_commit();
    }

    int arow = wm * 64 + (lane & 15);
    int akh  = lane >> 4;
    int brow = wn * 32 + (lane & 7) + ((lane >> 4) & 1) * 8;
    int bkh  = (lane >> 3) & 1;

    for (int kc = 0; kc < NC; kc++) {
        cp_wait<2>();
        __syncthreads();

        uint32_t base = sb + (kc & 3) * GST;
        #pragma unroll
        for (int ks = 0; ks < 2; ks++) {
            uint32_t af[4][4], bfr[2][4];
            #pragma unroll
            for (int ma = 0; ma < 4; ma++) {
                int r = arow + ma * 16;
                int c = ks * 2 + akh;
                ldm4(af[ma], base + (uint32_t)(r * 64 + ((c ^ (r & 3)) << 4)));
            }
            #pragma unroll
            for (int p = 0; p < 2; p++) {
                int r = brow + p * 16;
                int c = ks * 2 + bkh;
                ldm4(bfr[p], base + GOB + (uint32_t)(r * 64 + ((c ^ (r & 3)) << 4)));
            }
            #pragma unroll
            for (int ma = 0; ma < 4; ma++)
                #pragma unroll
                for (int na = 0; na < 4; na++)
                    mma16816(acc[ma][na], af[ma],
                             bfr[na >> 1][(na & 1) * 2],
                             bfr[na >> 1][(na & 1) * 2 + 1]);
        }
        __syncthreads();

        int kn = kc + 3;
        if (kn < NC) {
            uint32_t nbase = sb + (kn & 3) * GST;
            int kof = kn * 32;
            #pragma unroll
            for (int l = 0; l < 2; l++) {
                cpa16(nbase + doff[l],       pA + kof + soff[l]);
                cpa16(nbase + GOB + doff[l], pB + kof + soff[l]);
            }
        }
        cp_commit();
    }

    int l4 = lane >> 2, l2 = (lane & 3) * 2;
    #pragma unroll
    for (int ma = 0; ma < 4; ma++) {
        int grow0 = bm + wm * 64 + ma * 16 + l4;
        #pragma unroll
        for (int na = 0; na < 4; na++) {
            int gcol = bn + wn * 32 + na * 8 + l2;
            float b0 = __ldg(bias + gcol), b1 = __ldg(bias + gcol + 1);
            float v[4];
            v[0] = acc[ma][na][0] + b0;  v[1] = acc[ma][na][1] + b1;
            v[2] = acc[ma][na][2] + b0;  v[3] = acc[ma][na][3] + b1;
            if (GELU) {
                #pragma unroll
                for (int q = 0; q < 4; q++)
                    v[q] = 0.5f * v[q] * (1.0f + erff(v[q] * 0.70710678118654752f));
            }
            #pragma unroll
            for (int half = 0; half < 2; half++) {
                int grow = grow0 + half * 8;
                float va = v[half * 2], vb = v[half * 2 + 1];
                if (OUTMODE == 2) {
                    int part = gcol >> 9, rem = gcol & 511;
                    int head = rem >> 5, d = rem & 31;
                    int win = grow / 144, n = grow - win * 144;
                    size_t tb = ((size_t)part * NWIN * NHEAD + win * NHEAD + head) * TILE_BYTES;
                    *(uint32_t*)((char*)Ch + tb + tsw(n, d)) = packh(va, vb);
                } else {
                    *(uint32_t*)(Ch + (size_t)grow * N + gcol) = packh(va, vb);
                }
            }
        }
    }
}

// ---------------- fused GEMM + AdaLN + residual (BN = 512 full row) ----------
// C_row = A[row] @ B^T + bias;  y = LN(C_row)*scl + shift;  out = base + y
// PERM: row is window-layout; token index t = winrow_to_tok(row) for base/out.
#define LST 36864u          // stage: A 4KB @0, B 32KB @4096
#define LOB 4096u

template<bool PERM, bool HOUT>
__global__ __launch_bounds__(512)
void gemm_ln(const fp16* __restrict__ A, const fp16* __restrict__ B,
             const float* __restrict__ bias,
             const float* __restrict__ base,
             const float* __restrict__ shift, const float* __restrict__ scl,
             float* __restrict__ outf, fp16* __restrict__ outh, int K)
{
    extern __shared__ char smc[];
    uint32_t sb = smem_u32(smc);
    int tid = threadIdx.x, wid = tid >> 5, lane = tid & 31;
    int wm = wid >> 3, wn = wid & 7;        // 2 M-groups x 8 N-groups
    int bm = blockIdx.x * 64;

    // cp.async: thread t loads B row t (4 chunks); threads 0..63 also A row t.
    uint32_t bdoff[4], adoff[4];
    #pragma unroll
    for (int c = 0; c < 4; c++) {
        bdoff[c] = (uint32_t)(tid * 64 + ((c ^ (tid & 3)) << 4));
        adoff[c] = bdoff[c];                 // same formula, row=tid (tid<64)
    }
    const fp16* pB = B + (size_t)tid * K;
    const fp16* pA = A + (size_t)(bm + tid) * K;

    float acc[2][8][4];
    #pragma unroll
    for (int i = 0; i < 2; i++)
        #pragma unroll
        for (int j = 0; j < 8; j++)
            #pragma unroll
            for (int q = 0; q < 4; q++) acc[i][j][q] = 0.0f;

    int NC = K >> 5;
    #pragma unroll
    for (int s = 0; s < 2; s++) {
        uint32_t sbase = sb + s * LST;
        int kof = s * 32;
        #pragma unroll
        for (int c = 0; c < 4; c++) {
            cpa16(sbase + LOB + bdoff[c], pB + kof + c * 8);
            if (tid < 64) cpa16(sbase + adoff[c], pA + kof + c * 8);
        }
        cp_commit();
    }

    for (int kc = 0; kc < NC; kc++) {
        cp_wait<1>();
        __syncthreads();

        uint32_t sbase = sb + (kc % 3) * LST;
        #pragma unroll
        for (int ks = 0; ks < 2; ks++) {
            uint32_t af[2][4], bfr[4][4];
            #pragma unroll
            for (int ma = 0; ma < 2; ma++) {
                int r = wm * 32 + ma * 16 + (lane & 15);
                int c = ks * 2 + (lane >> 4);
                ldm4(af[ma], sbase + (uint32_t)(r * 64 + ((c ^ (r & 3)) << 4)));
            }
            #pragma unroll
            for (int nt = 0; nt < 4; nt++) {
                int r = wn * 64 + nt * 16 + (lane & 7) + ((lane >> 4) & 1) * 8;
                int c = ks * 2 + ((lane >> 3) & 1);
                ldm4(bfr[nt], sbase + LOB + (uint32_t)(r * 64 + ((c ^ (r & 3)) << 4)));
            }
            #pragma unroll
            for (int ma = 0; ma < 2; ma++)
                #pragma unroll
                for (int na = 0; na < 8; na++)
                    mma16816(acc[ma][na], af[ma],
                             bfr[na >> 1][(na & 1) * 2],
                             bfr[na >> 1][(na & 1) * 2 + 1]);
        }
        __syncthreads();

        int kn = kc + 2;
        if (kn < NC) {
            uint32_t nbase = sb + (kn % 3) * LST;
            int kof = kn * 32;
            #pragma unroll
            for (int c = 0; c < 4; c++) {
                cpa16(nbase + LOB + bdoff[c], pB + kof + c * 8);
                if (tid < 64) cpa16(nbase + adoff[c], pA + kof + c * 8);
            }
        }
        cp_commit();
    }
    cp_wait<0>();
    __syncthreads();            // all smem reads done; safe to alias for LN

    // per-thread cols: wn*64 + na*8 + (lane&3)*2
    int colb = wn * 64 + (lane & 3) * 2;
    float bcol[8][2], scv[8][2], shv[8][2];
    #pragma unroll
    for (int na = 0; na < 8; na++) {
        int col = colb + na * 8;
        bcol[na][0] = __ldg(bias + col);    bcol[na][1] = __ldg(bias + col + 1);
        scv[na][0]  = __ldg(scl + col);     scv[na][1]  = __ldg(scl + col + 1);
        shv[na][0]  = __ldg(shift + col);   shv[na][1]  = __ldg(shift + col + 1);
    }
    // add bias, accumulate partial row sums
    float* lns = (float*)smc;                  // [64][8]
    float* lnq = (float*)(smc + 2048);         // [64][8]
    float* lmean = (float*)(smc + 4096);       // [64]
    float* lrstd = (float*)(smc + 4352);       // [64]
    #pragma unroll
    for (int ma = 0; ma < 2; ma++) {
        #pragma unroll
        for (int half = 0; half < 2; half++) {
            float s = 0.0f, sq = 0.0f;
            #pragma unroll
            for (int na = 0; na < 8; na++) {
                float v0 = acc[ma][na][half * 2]     + bcol[na][0];
                float v1 = acc[ma][na][half * 2 + 1] + bcol[na][1];
                acc[ma][na][half * 2]     = v0;
                acc[ma][na][half * 2 + 1] = v1;
                s += v0 + v1;  sq += v0 * v0 + v1 * v1;
            }
            #pragma unroll
            for (int o = 1; o <= 2; o <<= 1) {
                s  += __shfl_xor_sync(0xffffffffu, s,  o);
                sq += __shfl_xor_sync(0xffffffffu, sq, o);
            }
            if ((lane & 3) == 0) {
                int lr = wm * 32 + ma * 16 + half * 8 + (lane >> 2);
                lns[lr * 8 + wn] = s;
                lnq[lr * 8 + wn] = sq;
            }
        }
    }
    __syncthreads();
    if (tid < 64) {
        float s = 0.0f, q = 0.0f;
        #pragma unroll
        for (int w = 0; w < 8; w++) { s += lns[tid * 8 + w]; q += lnq[tid * 8 + w]; }
        float mean = s * (1.0f / 512.0f);
        float var  = q * (1.0f / 512.0f) - mean * mean;
        lmean[tid] = mean;
        lrstd[tid] = rsqrtf(var + 1e-5f);
    }
    __syncthreads();

    #pragma unroll
    for (int ma = 0; ma < 2; ma++) {
        #pragma unroll
        for (int half = 0; half < 2; half++) {
            int lr = wm * 32 + ma * 16 + half * 8 + (lane >> 2);
            int grow = bm + lr;
            int t = PERM ? winrow_to_tok(grow) : grow;
            float mean = lmean[lr], rstd = lrstd[lr];
            const float* brow = base + (size_t)t * DMODEL;
            float* frow = outf + (size_t)t * DMODEL;
            #pragma unroll
            for (int na = 0; na < 8; na++) {
                int col = colb + na * 8;
                float2 bx = *(const float2*)(brow + col);
                float o0 = bx.x + (acc[ma][na][half*2]     - mean) * rstd * scv[na][0] + shv[na][0];
                float o1 = bx.y + (acc[ma][na][half*2 + 1] - mean) * rstd * scv[na][1] + shv[na][1];
                float2 st; st.x = o0; st.y = o1;
                *(float2*)(frow + col) = st;
                if (HOUT)
                    *(uint32_t*)(outh + (size_t)t * DMODEL + col) = packh(o0, o1);
            }
        }
    }
}

// ---------------- mod GEMV ---------------------------------------------------
__global__ void mod_kernel(const float* __restrict__ c,
                           const float* __restrict__ w1, const float* __restrict__ b1,
                           const float* __restrict__ w2, const float* __restrict__ b2,
                           float* __restrict__ gmod)
{
    __shared__ float sc[512];
    int tid = threadIdx.x;
    for (int i = tid; i < 512; i += 256) {
        float v = c[i];
        sc[i] = v / (1.0f + __expf(-v));
    }
    __syncthreads();
    int o = blockIdx.x * 256 + tid;
    const float* w; const float* b; int col;
    if (o < 1024) { w = w1; b = b1; col = o; }
    else          { w = w2; b = b2; col = o - 1024; }
    float acc = b[col];
    for (int k = 0; k < 512; k++)
        acc += sc[k] * w[k * 1024 + col];
    gmod[o] = acc;
}

// ---------------- shift + window partition -> fp16 ---------------------------
__global__ void partition_kernel(const float* __restrict__ x, fp16* __restrict__ xw)
{
    int row = blockIdx.x;
    int tid = threadIdx.x;
    size_t src = (size_t)winrow_to_tok(row) * DMODEL;
    float4 f = ((const float4*)(x + src))[tid];
    size_t o = (size_t)row * DMODEL + tid * 4;
    *(uint2*)(xw + o) = make_uint2(packh(f.x, f.y), packh(f.z, f.w));
}

// ---------------- windowed attention -----------------------------------------
#define AT_Q   0u
#define AT_K   9216u
#define AT_V   18432u
#define AT_LBL 27648u
#define AT_TOTAL 28224u

__global__ __launch_bounds__(288)
void attn_mma(const fp16* __restrict__ qkv, fp16* __restrict__ aw)
{
    extern __shared__ char sm[];
    uint32_t sb = smem_u32(sm);
    int tid = threadIdx.x, warp = tid >> 5, lane = tid & 31;
    int bid = blockIdx.x;
    int win = bid >> 4, head = bid & 15;
    int wb = win & 7, hb = (win >> 3) & 15, cb = win >> 7;
    int* lbls = (int*)(sm + AT_LBL);

    {
        size_t t0 = ((size_t)win * NHEAD + head) * TILE_BYTES;
        size_t stp = (size_t)NWIN * NHEAD * TILE_BYTES;
        const char* p = (const char*)qkv;
        #pragma unroll
        for (int it = 0; it < 2; it++) {
            uint32_t off = (uint32_t)((it * 288 + tid) * 16);
            cpa16(sb + AT_Q + off, p + t0 + off);
            cpa16(sb + AT_K + off, p + t0 + stp + off);
            cpa16(sb + AT_V + off, p + t0 + 2 * stp + off);
        }
        cp_commit();
    }
    for (int n = tid; n < WTOK; n += 288) {
        int i = n / 72, rem = n % 72, j = rem / 12, k = rem % 12;
        int cs = cb * 2 + i, hs = hb * 6 + j, ws = wb * 12 + k;
        int lc = cs < 2 ? 0 : (cs < 3 ? 1 : 2);
        int lh = hs < 90 ? 0 : (hs < 93 ? 1 : 2);
        int lw = ws < 84 ? 0 : (ws < 90 ? 1 : 2);
        lbls[n] = lc * 9 + lh * 3 + lw;
    }
    cp_wait<0>();
    __syncthreads();

    int R = warp * 16;

    uint32_t qf[2][4];
    #pragma unroll
    for (int t = 0; t < 2; t++) {
        int r = R + (lane & 15);
        int c = t * 2 + (lane >> 4);
        ldm4(qf[t], sb + AT_Q + (uint32_t)(r * 64 + ((c ^ (r & 3)) << 4)));
    }

    float acc[18][4];
    #pragma unroll
    for (int nt = 0; nt < 18; nt++)
        #pragma unroll
        for (int q = 0; q < 4; q++) acc[nt][q] = 0.0f;

    #pragma unroll
    for (int t = 0; t < 2; t++) {
        #pragma unroll
        for (int jt = 0; jt < 9; jt++) {
            int r = jt * 16 + (lane & 7) + ((lane >> 4) & 1) * 8;
            int c = t * 2 + ((lane >> 3) & 1);
            uint32_t kf[4];
            ldm4(kf, sb + AT_K + (uint32_t)(r * 64 + ((c ^ (r & 3)) << 4)));
            mma16816(acc[2*jt],   qf[t], kf[0], kf[1]);
            mma16816(acc[2*jt+1], qf[t], kf[2], kf[3]);
        }
    }

    const float scale = 0.17677669529663688f;
    int r0 = R + (lane >> 2), r1 = r0 + 8;
    int li0 = lbls[r0], li1 = lbls[r1];
    float m0 = -1e30f, m1 = -1e30f;
    #pragma unroll
    for (int nt = 0; nt < 18; nt++) {
        int j0 = nt * 8 + (lane & 3) * 2;
        int lj0 = lbls[j0], lj1 = lbls[j0 + 1];
        acc[nt][0] = acc[nt][0] * scale + (lj0 == li0 ? 0.0f : -100.0f);
        acc[nt][1] = acc[nt][1] * scale + (lj1 == li0 ? 0.0f : -100.0f);
        acc[nt][2] = acc[nt][2] * scale + (lj0 == li1 ? 0.0f : -100.0f);
        acc[nt][3] = acc[nt][3] * scale + (lj1 == li1 ? 0.0f : -100.0f);
        m0 = fmaxf(m0, fmaxf(acc[nt][0], acc[nt][1]));
        m1 = fmaxf(m1, fmaxf(acc[nt][2], acc[nt][3]));
    }
    #pragma unroll
    for (int o = 1; o <= 2; o <<= 1) {
        m0 = fmaxf(m0, __shfl_xor_sync(0xffffffffu, m0, o));
        m1 = fmaxf(m1, __shfl_xor_sync(0xffffffffu, m1, o));
    }
    float s0 = 0.0f, s1 = 0.0f;
    #pragma unroll
    for (int nt = 0; nt < 18; nt++) {
        acc[nt][0] = __expf(acc[nt][0] - m0);  s0 += acc[nt][0];
        acc[nt][1] = __expf(acc[nt][1] - m0);  s0 += acc[nt][1];
        acc[nt][2] = __expf(acc[nt][2] - m1);  s1 += acc[nt][2];
        acc[nt][3] = __expf(acc[nt][3] - m1);  s1 += acc[nt][3];
    }
    #pragma unroll
    for (int o = 1; o <= 2; o <<= 1) {
        s0 += __shfl_xor_sync(0xffffffffu, s0, o);
        s1 += __shfl_xor_sync(0xffffffffu, s1, o);
    }
    float i0 = 1.0f / s0, i1 = 1.0f / s1;
    #pragma unroll
    for (int nt = 0; nt < 18; nt++) {
        acc[nt][0] *= i0; acc[nt][1] *= i0;
        acc[nt][2] *= i1; acc[nt][3] *= i1;
    }

    float pv[4][4];
    #pragma unroll
    for (int na = 0; na < 4; na++)
        #pragma unroll
        for (int q = 0; q < 4; q++) pv[na][q] = 0.0f;

    #pragma unroll
    for (int jt = 0; jt < 9; jt++) {
        uint32_t pa[4];
        pa[0] = packh(acc[2*jt][0],   acc[2*jt][1]);
        pa[1] = packh(acc[2*jt][2],   acc[2*jt][3]);
        pa[2] = packh(acc[2*jt+1][0], acc[2*jt+1][1]);
        pa[3] = packh(acc[2*jt+1][2], acc[2*jt+1][3]);
        #pragma unroll
        for (int dt = 0; dt < 2; dt++) {
            int r = jt * 16 + (lane & 15);
            int cblk = dt * 2 + (lane >> 4);
            uint32_t vf[4];
            ldm4t(vf, sb + AT_V + (uint32_t)(r * 64 + ((cblk ^ (r & 3)) << 4)));
            mma16816(pv[dt*2],   pa, vf[0], vf[1]);
            mma16816(pv[dt*2+1], pa, vf[2], vf[3]);
        }
    }

    #pragma unroll
    for (int na = 0; na < 4; na++) {
        int col = head * HDIM + na * 8 + (lane & 3) * 2;
        #pragma unroll
        for (int half = 0; half < 2; half++) {
            int grow = win * WTOK + (half ? r1 : r0);
            *(uint32_t*)(aw + (size_t)grow * DMODEL + col) =
                packh(pv[na][half * 2], pv[na][half * 2 + 1]);
        }
    }
}

// ---------------------------------------------------------------------------
extern "C" void kernel_launch(void* const* d_in, const int* in_sizes, int n_in,
                              void* d_out, int out_size)
{
    (void)in_sizes; (void)n_in; (void)out_size;
    const float* x      = (const float*)d_in[0];
    const float* c      = (const float*)d_in[1];
    const float* w_qkv  = (const float*)d_in[2];
    const float* b_qkv  = (const float*)d_in[3];
    const float* w_proj = (const float*)d_in[4];
    const float* b_proj = (const float*)d_in[5];
    const float* w_fc1  = (const float*)d_in[6];
    const float* b_fc1  = (const float*)d_in[7];
    const float* w_fc2  = (const float*)d_in[8];
    const float* b_fc2  = (const float*)d_in[9];
    const float* w_mod1 = (const float*)d_in[10];
    const float* b_mod1 = (const float*)d_in[11];
    const float* w_mod2 = (const float*)d_in[12];
    const float* b_mod2 = (const float*)d_in[13];
    float* out = (float*)d_out;

    float *p_x1, *p_mod;
    fp16 *p_xw, *p_q, *p_aw, *p_x1f, *p_h;
    cudaGetSymbolAddress((void**)&p_x1,  g_x1);
    cudaGetSymbolAddress((void**)&p_mod, g_mod);
    cudaGetSymbolAddress((void**)&p_xw,  g_xw);
    cudaGetSymbolAddress((void**)&p_q,   g_qkv);
    cudaGetSymbolAddress((void**)&p_aw,  g_aw);
    cudaGetSymbolAddress((void**)&p_x1f, g_x1f);
    cudaGetSymbolAddress((void**)&p_h,   g_h);

    fp16 *qw, *pw, *f1w, *f2w;
    cudaGetSymbolAddress((void**)&qw,  g_wqkv);
    cudaGetSymbolAddress((void**)&pw,  g_wproj);
    cudaGetSymbolAddress((void**)&f1w, g_wfc1);
    cudaGetSymbolAddress((void**)&f2w, g_wfc2);

    const int SMEM = 65536;
    const int LSMEM = 3 * 36864;   // 110592
    cudaFuncSetAttribute(gemm_mma<false,2>, cudaFuncAttributeMaxDynamicSharedMemorySize, SMEM);
    cudaFuncSetAttribute(gemm_mma<true,1>,  cudaFuncAttributeMaxDynamicSharedMemorySize, SMEM);
    cudaFuncSetAttribute(gemm_ln<true,true>,   cudaFuncAttributeMaxDynamicSharedMemorySize, LSMEM);
    cudaFuncSetAttribute(gemm_ln<false,false>, cudaFuncAttributeMaxDynamicSharedMemorySize, LSMEM);
    cudaFuncSetAttribute(attn_mma, cudaFuncAttributeMaxDynamicSharedMemorySize, AT_TOTAL);

    dim3 wcb(32, 8);
    wconv_kernel<<<dim3(QKVDIM / 32, DMODEL / 32), wcb>>>(w_qkv,  qw,  DMODEL, QKVDIM);
    wconv_kernel<<<dim3(DMODEL / 32, DMODEL / 32), wcb>>>(w_proj, pw,  DMODEL, DMODEL);
    wconv_kernel<<<dim3(FFNDIM / 32, DMODEL / 32), wcb>>>(w_fc1,  f1w, DMODEL, FFNDIM);
    wconv_kernel<<<dim3(DMODEL / 32, FFNDIM / 32), wcb>>>(w_fc2,  f2w, FFNDIM, DMODEL);

    mod_kernel<<<8, 256>>>(c, w_mod1, b_mod1, w_mod2, b_mod2, p_mod);
    partition_kernel<<<L_TOK, 128>>>(x, p_xw);

    gemm_mma<false,2><<<dim3(QKVDIM / 128, L_TOK / 128), 256, SMEM>>>(
        p_xw, qw, b_qkv, p_q, L_TOK, QKVDIM, DMODEL);
    attn_mma<<<NWIN * NHEAD, 288, AT_TOTAL>>>(p_q, p_aw);
    // proj + AdaLN1 + residual (window-reverse fused): x1 = x + adaln1(proj(aw))
    gemm_ln<true,true><<<L_TOK / 64, 512, LSMEM>>>(
        p_aw, pw, b_proj, x, p_mod, p_mod + 512, p_x1, p_x1f, DMODEL);
    gemm_mma<true,1><<<dim3(FFNDIM / 128, L_TOK / 128), 256, SMEM>>>(
        p_x1f, f1w, b_fc1, p_h, L_TOK, FFNDIM, DMODEL);
    // fc2 + AdaLN2 + residual: out = x1 + adaln2(fc2(h))
    gemm_ln<false,false><<<L_TOK / 64, 512, LSMEM>>>(
        p_h, f2w, b_fc2, p_x1, p_mod + 1024, p_mod + 1536, out, nullptr, FFNDIM);
}

// round 14
// speedup vs baseline: 1.0190x; 1.0190x over previous
#include <cuda_runtime.h>
#include <cuda_fp16.h>
#include <math.h>
#include <stdint.h>

// ---------------------------------------------------------------------------
// Swin3D block, fp16 mma.sync. R12/R13/R14: revert R11's gemm_ln fusion
// (regressed: BN=512 blocks doubled weight L2 traffic); back to R9 structure
// with separate adaln kernels. Change: GEMM tile 128x128 -> 128x256
// (warp 64x64), MMA-per-ldmatrix density 2.67 -> 4.0.
// (Third submission — R12/R13 were broker-container failures; kernel never ran.)
// ---------------------------------------------------------------------------

#define L_TOK   36864
#define DMODEL  512
#define QKVDIM  1536
#define FFNDIM  2048
#define NWIN    256
#define WTOK    144
#define NHEAD   16
#define HDIM    32

typedef __half fp16;

// ---------------- scratch ---------------------------------------------------
__device__ fp16  g_xw  [L_TOK * DMODEL];
__device__ fp16  g_qkv [L_TOK * QKVDIM];   // attention-tile layout
__device__ fp16  g_aw  [L_TOK * DMODEL];
__device__ float g_pro [L_TOK * DMODEL];
__device__ float g_x1  [L_TOK * DMODEL];
__device__ fp16  g_x1f [L_TOK * DMODEL];
__device__ fp16  g_h   [L_TOK * FFNDIM];
__device__ float g_h2  [L_TOK * DMODEL];
__device__ float g_mod [2048];

__device__ fp16 g_wqkv [QKVDIM * DMODEL];
__device__ fp16 g_wproj[DMODEL * DMODEL];
__device__ fp16 g_wfc1 [FFNDIM * DMODEL];
__device__ fp16 g_wfc2 [DMODEL * FFNDIM];

#define TILE_BYTES 9216

// ---------------- helpers ---------------------------------------------------
__device__ __forceinline__ uint32_t smem_u32(const void* p) {
    uint32_t a;
    asm("{ .reg .u64 t; cvta.to.shared.u64 t, %1; cvt.u32.u64 %0, t; }" : "=r"(a) : "l"(p));
    return a;
}
__device__ __forceinline__ uint32_t packh(float a, float b) {
    uint32_t r;
    asm("cvt.rn.f16x2.f32 %0, %1, %2;" : "=r"(r) : "f"(b), "f"(a));
    return r;
}
__device__ __forceinline__ void cpa16(uint32_t dst, const void* src) {
    asm volatile("cp.async.cg.shared.global [%0], [%1], 16;" :: "r"(dst), "l"(src) : "memory");
}
__device__ __forceinline__ void cp_commit() {
    asm volatile("cp.async.commit_group;" ::: "memory");
}
template<int N>
__device__ __forceinline__ void cp_wait() {
    asm volatile("cp.async.wait_group %0;" :: "n"(N) : "memory");
}
__device__ __forceinline__ void ldm4(uint32_t* r, uint32_t addr) {
    asm volatile("ldmatrix.sync.aligned.m8n8.x4.shared.b16 {%0,%1,%2,%3}, [%4];"
                 : "=r"(r[0]), "=r"(r[1]), "=r"(r[2]), "=r"(r[3]) : "r"(addr));
}
__device__ __forceinline__ void ldm4t(uint32_t* r, uint32_t addr) {
    asm volatile("ldmatrix.sync.aligned.m8n8.x4.trans.shared.b16 {%0,%1,%2,%3}, [%4];"
                 : "=r"(r[0]), "=r"(r[1]), "=r"(r[2]), "=r"(r[3]) : "r"(addr));
}
__device__ __forceinline__ void mma16816(float* d, const uint32_t* a,
                                         uint32_t b0, uint32_t b1) {
    asm volatile(
        "mma.sync.aligned.m16n8k16.row.col.f32.f16.f16.f32 "
        "{%0,%1,%2,%3},{%4,%5,%6,%7},{%8,%9},{%0,%1,%2,%3};"
        : "+f"(d[0]), "+f"(d[1]), "+f"(d[2]), "+f"(d[3])
        : "r"(a[0]), "r"(a[1]), "r"(a[2]), "r"(a[3]), "r"(b0), "r"(b1));
}
__device__ __forceinline__ uint32_t tsw(int n, int d) {
    return (uint32_t)(n * 64 + (((d >> 3) ^ (n & 3)) << 4) + (d & 7) * 2);
}
__device__ __forceinline__ int winrow_to_tok(int row) {
    int win = row / WTOK, n = row % WTOK;
    int wb = win & 7, hb = (win >> 3) & 15, cb = win >> 7;
    int i = n / 72, rem = n % 72, j = rem / 12, k = rem % 12;
    int cs = cb * 2 + i, hs = hb * 6 + j, ws = wb * 12 + k;
    int c0 = (cs + 1) & 3;
    int h0 = hs + 3;  if (h0 >= 96) h0 -= 96;
    int w0 = ws + 6;  if (w0 >= 96) w0 -= 96;
    return (c0 * 96 + h0) * 96 + w0;
}

// ---------------- weight transpose + fp16 ------------------------------------
__global__ void wconv_kernel(const float* __restrict__ w,
                             fp16* __restrict__ oh, int K, int N)
{
    __shared__ float t[32][33];
    int n0 = blockIdx.x * 32, k0 = blockIdx.y * 32;
    int tx = threadIdx.x, ty = threadIdx.y;
    for (int i = ty; i < 32; i += 8)
        t[i][tx] = w[(size_t)(k0 + i) * N + n0 + tx];
    __syncthreads();
    for (int i = ty; i < 32; i += 8)
        oh[(size_t)(n0 + i) * K + k0 + tx] = __float2half(t[tx][i]);
}

// ---------------- mma.sync fp16 GEMM (128x256 tile, 4-stage ring) ------------
// warp tile 64x64 (2 M-groups x 4 N-groups of warps).
// OUTMODE: 0 = fp32 Cf, 1 = fp16 Ch, 2 = qkv attention tiles
#define GST 24576u          // stage: A 8KB + B 16KB
#define GOB 8192u

template<bool GELU, int OUTMODE>
__global__ __launch_bounds__(256)
void gemm_mma(const fp16* __restrict__ A, const fp16* __restrict__ B,
              const float* __restrict__ bias,
              float* __restrict__ Cf, fp16* __restrict__ Ch,
              int M, int N, int K)
{
    extern __shared__ char smc[];
    uint32_t sb = smem_u32(smc);
    int tid = threadIdx.x, wid = tid >> 5, lane = tid & 31;
    int wm = wid & 1, wn = wid >> 1;            // warp tile 64x64
    int bm = blockIdx.y * 128, bn = blockIdx.x * 256;

    // cp.async: A 512 chunks (2/thread), B 1024 chunks (4/thread = row tid)
    int aro = tid >> 1, ac0 = (tid & 1) * 2;    // A row, first chunk
    uint32_t adoff[2];
    #pragma unroll
    for (int l = 0; l < 2; l++) {
        int c = ac0 + l;
        adoff[l] = (uint32_t)(aro * 64 + ((c ^ (aro & 3)) << 4));
    }
    uint32_t bdoff[4];
    #pragma unroll
    for (int c = 0; c < 4; c++)
        bdoff[c] = (uint32_t)(tid * 64 + ((c ^ (tid & 3)) << 4));
    const fp16* pA = A + (size_t)(bm + aro) * K + ac0 * 8;
    const fp16* pB = B + (size_t)(bn + tid) * K;

    float acc[4][8][4];
    #pragma unroll
    for (int i = 0; i < 4; i++)
        #pragma unroll
        for (int j = 0; j < 8; j++)
            #pragma unroll
            for (int q = 0; q < 4; q++) acc[i][j][q] = 0.0f;

    int NC = K >> 5;
    #pragma unroll
    for (int s = 0; s < 3; s++) {
        if (s < NC) {
            uint32_t base = sb + s * GST;
            int kof = s * 32;
            #pragma unroll
            for (int l = 0; l < 2; l++)
                cpa16(base + adoff[l], pA + kof + l * 8);
            #pragma unroll
            for (int c = 0; c < 4; c++)
                cpa16(base + GOB + bdoff[c], pB + kof + c * 8);
        }
        cp_commit();
    }

    int arow = wm * 64 + (lane & 15);
    int akh  = lane >> 4;
    int brow0 = wn * 64 + (lane & 7) + ((lane >> 4) & 1) * 8;
    int bkh  = (lane >> 3) & 1;

    for (int kc = 0; kc < NC; kc++) {
        cp_wait<2>();
        __syncthreads();

        uint32_t base = sb + (kc & 3) * GST;
        #pragma unroll
        for (int ks = 0; ks < 2; ks++) {
            uint32_t af[4][4], bfr[4][4];
            #pragma unroll
            for (int ma = 0; ma < 4; ma++) {
                int r = arow + ma * 16;
                int c = ks * 2 + akh;
                ldm4(af[ma], base + (uint32_t)(r * 64 + ((c ^ (r & 3)) << 4)));
            }
            #pragma unroll
            for (int nt = 0; nt < 4; nt++) {
                int r = brow0 + nt * 16;
                int c = ks * 2 + bkh;
                ldm4(bfr[nt], base + GOB + (uint32_t)(r * 64 + ((c ^ (r & 3)) << 4)));
            }
            #pragma unroll
            for (int ma = 0; ma < 4; ma++)
                #pragma unroll
                for (int na = 0; na < 8; na++)
                    mma16816(acc[ma][na], af[ma],
                             bfr[na >> 1][(na & 1) * 2],
                             bfr[na >> 1][(na & 1) * 2 + 1]);
        }
        __syncthreads();

        int kn = kc + 3;
        if (kn < NC) {
            uint32_t nbase = sb + (kn & 3) * GST;
            int kof = kn * 32;
            #pragma unroll
            for (int l = 0; l < 2; l++)
                cpa16(nbase + adoff[l], pA + kof + l * 8);
            #pragma unroll
            for (int c = 0; c < 4; c++)
                cpa16(nbase + GOB + bdoff[c], pB + kof + c * 8);
        }
        cp_commit();
    }

    // ---- epilogue
    int l4 = lane >> 2, l2 = (lane & 3) * 2;
    #pragma unroll
    for (int ma = 0; ma < 4; ma++) {
        int grow0 = bm + wm * 64 + ma * 16 + l4;
        #pragma unroll
        for (int na = 0; na < 8; na++) {
            int gcol = bn + wn * 64 + na * 8 + l2;
            float b0 = __ldg(bias + gcol), b1 = __ldg(bias + gcol + 1);
            float v[4];
            v[0] = acc[ma][na][0] + b0;  v[1] = acc[ma][na][1] + b1;
            v[2] = acc[ma][na][2] + b0;  v[3] = acc[ma][na][3] + b1;
            if (GELU) {
                #pragma unroll
                for (int q = 0; q < 4; q++)
                    v[q] = 0.5f * v[q] * (1.0f + erff(v[q] * 0.70710678118654752f));
            }
            #pragma unroll
            for (int half = 0; half < 2; half++) {
                int grow = grow0 + half * 8;
                float va = v[half * 2], vb = v[half * 2 + 1];
                if (OUTMODE == 2) {
                    int part = gcol >> 9, rem = gcol & 511;
                    int head = rem >> 5, d = rem & 31;
                    int win = grow / 144, n = grow - win * 144;
                    size_t tb = ((size_t)part * NWIN * NHEAD + win * NHEAD + head) * TILE_BYTES;
                    *(uint32_t*)((char*)Ch + tb + tsw(n, d)) = packh(va, vb);
                } else if (OUTMODE == 1) {
                    *(uint32_t*)(Ch + (size_t)grow * N + gcol) = packh(va, vb);
                } else {
                    float2 st; st.x = va; st.y = vb;
                    *(float2*)(Cf + (size_t)grow * N + gcol) = st;
                }
            }
        }
    }
}

// ---------------- mod GEMV ---------------------------------------------------
__global__ void mod_kernel(const float* __restrict__ c,
                           const float* __restrict__ w1, const float* __restrict__ b1,
                           const float* __restrict__ w2, const float* __restrict__ b2,
                           float* __restrict__ gmod)
{
    __shared__ float sc[512];
    int tid = threadIdx.x;
    for (int i = tid; i < 512; i += 256) {
        float v = c[i];
        sc[i] = v / (1.0f + __expf(-v));
    }
    __syncthreads();
    int o = blockIdx.x * 256 + tid;
    const float* w; const float* b; int col;
    if (o < 1024) { w = w1; b = b1; col = o; }
    else          { w = w2; b = b2; col = o - 1024; }
    float acc = b[col];
    for (int k = 0; k < 512; k++)
        acc += sc[k] * w[k * 1024 + col];
    gmod[o] = acc;
}

// ---------------- shift + window partition -> fp16 ---------------------------
__global__ void partition_kernel(const float* __restrict__ x, fp16* __restrict__ xw)
{
    int row = blockIdx.x;
    int tid = threadIdx.x;
    size_t src = (size_t)winrow_to_tok(row) * DMODEL;
    float4 f = ((const float4*)(x + src))[tid];
    size_t o = (size_t)row * DMODEL + tid * 4;
    *(uint2*)(xw + o) = make_uint2(packh(f.x, f.y), packh(f.z, f.w));
}

// ---------------- windowed attention -----------------------------------------
#define AT_Q   0u
#define AT_K   9216u
#define AT_V   18432u
#define AT_LBL 27648u
#define AT_TOTAL 28224u

__global__ __launch_bounds__(288)
void attn_mma(const fp16* __restrict__ qkv, fp16* __restrict__ aw)
{
    extern __shared__ char sm[];
    uint32_t sb = smem_u32(sm);
    int tid = threadIdx.x, warp = tid >> 5, lane = tid & 31;
    int bid = blockIdx.x;
    int win = bid >> 4, head = bid & 15;
    int wb = win & 7, hb = (win >> 3) & 15, cb = win >> 7;
    int* lbls = (int*)(sm + AT_LBL);

    {
        size_t t0 = ((size_t)win * NHEAD + head) * TILE_BYTES;
        size_t stp = (size_t)NWIN * NHEAD * TILE_BYTES;
        const char* p = (const char*)qkv;
        #pragma unroll
        for (int it = 0; it < 2; it++) {
            uint32_t off = (uint32_t)((it * 288 + tid) * 16);
            cpa16(sb + AT_Q + off, p + t0 + off);
            cpa16(sb + AT_K + off, p + t0 + stp + off);
            cpa16(sb + AT_V + off, p + t0 + 2 * stp + off);
        }
        cp_commit();
    }
    for (int n = tid; n < WTOK; n += 288) {
        int i = n / 72, rem = n % 72, j = rem / 12, k = rem % 12;
        int cs = cb * 2 + i, hs = hb * 6 + j, ws = wb * 12 + k;
        int lc = cs < 2 ? 0 : (cs < 3 ? 1 : 2);
        int lh = hs < 90 ? 0 : (hs < 93 ? 1 : 2);
        int lw = ws < 84 ? 0 : (ws < 90 ? 1 : 2);
        lbls[n] = lc * 9 + lh * 3 + lw;
    }
    cp_wait<0>();
    __syncthreads();

    int R = warp * 16;

    uint32_t qf[2][4];
    #pragma unroll
    for (int t = 0; t < 2; t++) {
        int r = R + (lane & 15);
        int c = t * 2 + (lane >> 4);
        ldm4(qf[t], sb + AT_Q + (uint32_t)(r * 64 + ((c ^ (r & 3)) << 4)));
    }

    float acc[18][4];
    #pragma unroll
    for (int nt = 0; nt < 18; nt++)
        #pragma unroll
        for (int q = 0; q < 4; q++) acc[nt][q] = 0.0f;

    #pragma unroll
    for (int t = 0; t < 2; t++) {
        #pragma unroll
        for (int jt = 0; jt < 9; jt++) {
            int r = jt * 16 + (lane & 7) + ((lane >> 4) & 1) * 8;
            int c = t * 2 + ((lane >> 3) & 1);
            uint32_t kf[4];
            ldm4(kf, sb + AT_K + (uint32_t)(r * 64 + ((c ^ (r & 3)) << 4)));
            mma16816(acc[2*jt],   qf[t], kf[0], kf[1]);
            mma16816(acc[2*jt+1], qf[t], kf[2], kf[3]);
        }
    }

    const float scale = 0.17677669529663688f;
    int r0 = R + (lane >> 2), r1 = r0 + 8;
    int li0 = lbls[r0], li1 = lbls[r1];
    float m0 = -1e30f, m1 = -1e30f;
    #pragma unroll
    for (int nt = 0; nt < 18; nt++) {
        int j0 = nt * 8 + (lane & 3) * 2;
        int lj0 = lbls[j0], lj1 = lbls[j0 + 1];
        acc[nt][0] = acc[nt][0] * scale + (lj0 == li0 ? 0.0f : -100.0f);
        acc[nt][1] = acc[nt][1] * scale + (lj1 == li0 ? 0.0f : -100.0f);
        acc[nt][2] = acc[nt][2] * scale + (lj0 == li1 ? 0.0f : -100.0f);
        acc[nt][3] = acc[nt][3] * scale + (lj1 == li1 ? 0.0f : -100.0f);
        m0 = fmaxf(m0, fmaxf(acc[nt][0], acc[nt][1]));
        m1 = fmaxf(m1, fmaxf(acc[nt][2], acc[nt][3]));
    }
    #pragma unroll
    for (int o = 1; o <= 2; o <<= 1) {
        m0 = fmaxf(m0, __shfl_xor_sync(0xffffffffu, m0, o));
        m1 = fmaxf(m1, __shfl_xor_sync(0xffffffffu, m1, o));
    }
    float s0 = 0.0f, s1 = 0.0f;
    #pragma unroll
    for (int nt = 0; nt < 18; nt++) {
        acc[nt][0] = __expf(acc[nt][0] - m0);  s0 += acc[nt][0];
        acc[nt][1] = __expf(acc[nt][1] - m0);  s0 += acc[nt][1];
        acc[nt][2] = __expf(acc[nt][2] - m1);  s1 += acc[nt][2];
        acc[nt][3] = __expf(acc[nt][3] - m1);  s1 += acc[nt][3];
    }
    #pragma unroll
    for (int o = 1; o <= 2; o <<= 1) {
        s0 += __shfl_xor_sync(0xffffffffu, s0, o);
        s1 += __shfl_xor_sync(0xffffffffu, s1, o);
    }
    float i0 = 1.0f / s0, i1 = 1.0f / s1;
    #pragma unroll
    for (int nt = 0; nt < 18; nt++) {
        acc[nt][0] *= i0; acc[nt][1] *= i0;
        acc[nt][2] *= i1; acc[nt][3] *= i1;
    }

    float pv[4][4];
    #pragma unroll
    for (int na = 0; na < 4; na++)
        #pragma unroll
        for (int q = 0; q < 4; q++) pv[na][q] = 0.0f;

    #pragma unroll
    for (int jt = 0; jt < 9; jt++) {
        uint32_t pa[4];
        pa[0] = packh(acc[2*jt][0],   acc[2*jt][1]);
        pa[1] = packh(acc[2*jt][2],   acc[2*jt][3]);
        pa[2] = packh(acc[2*jt+1][0], acc[2*jt+1][1]);
        pa[3] = packh(acc[2*jt+1][2], acc[2*jt+1][3]);
        #pragma unroll
        for (int dt = 0; dt < 2; dt++) {
            int r = jt * 16 + (lane & 15);
            int cblk = dt * 2 + (lane >> 4);
            uint32_t vf[4];
            ldm4t(vf, sb + AT_V + (uint32_t)(r * 64 + ((cblk ^ (r & 3)) << 4)));
            mma16816(pv[dt*2],   pa, vf[0], vf[1]);
            mma16816(pv[dt*2+1], pa, vf[2], vf[3]);
        }
    }

    #pragma unroll
    for (int na = 0; na < 4; na++) {
        int col = head * HDIM + na * 8 + (lane & 3) * 2;
        #pragma unroll
        for (int half = 0; half < 2; half++) {
            int grow = win * WTOK + (half ? r1 : r0);
            *(uint32_t*)(aw + (size_t)grow * DMODEL + col) =
                packh(pv[na][half * 2], pv[na][half * 2 + 1]);
        }
    }
}

// ---------------- AdaLN + residual -------------------------------------------
template<bool PERM, bool HOUT>
__global__ __launch_bounds__(128)
void adaln_kernel(const float* __restrict__ base, const float* __restrict__ src,
                  const float* __restrict__ shift, const float* __restrict__ scl,
                  float* __restrict__ out, fp16* __restrict__ oh)
{
    int t = blockIdx.x, tid = threadIdx.x;
    size_t srow;
    if (PERM) {
        int c0 = t / (96 * 96); int r = t % (96 * 96);
        int h0 = r / 96, w0 = r % 96;
        int cs = (c0 + 3) & 3;
        int hs = h0 - 3; if (hs < 0) hs += 96;
        int ws = w0 - 6; if (ws < 0) ws += 96;
        int cb = cs >> 1, i = cs & 1;
        int hb = hs / 6,  j = hs % 6;
        int wb = ws / 12, k = ws % 12;
        srow = (size_t)(((cb * 16 + hb) * 8 + wb) * WTOK + (i * 6 + j) * 12 + k);
    } else {
        srow = (size_t)t;
    }
    float4 v = ((const float4*)(src + srow * DMODEL))[tid];
    float s  = v.x + v.y + v.z + v.w;
    float sq = v.x * v.x + v.y * v.y + v.z * v.z + v.w * v.w;
    for (int o = 16; o; o >>= 1) {
        s  += __shfl_xor_sync(0xffffffffu, s,  o);
        sq += __shfl_xor_sync(0xffffffffu, sq, o);
    }
    __shared__ float rs[4], rq[4];
    int w = tid >> 5, ln = tid & 31;
    if (ln == 0) { rs[w] = s; rq[w] = sq; }
    __syncthreads();
    float S = rs[0] + rs[1] + rs[2] + rs[3];
    float Q = rq[0] + rq[1] + rq[2] + rq[3];
    float mean = S * (1.0f / 512.0f);
    float var  = Q * (1.0f / 512.0f) - mean * mean;
    float rstd = rsqrtf(var + 1e-5f);

    float4 sh = ((const float4*)shift)[tid];
    float4 sc = ((const float4*)scl)[tid];
    float4 bx = ((const float4*)(base + (size_t)t * DMODEL))[tid];
    float4 o;
    o.x = bx.x + (v.x - mean) * rstd * sc.x + sh.x;
    o.y = bx.y + (v.y - mean) * rstd * sc.y + sh.y;
    o.z = bx.z + (v.z - mean) * rstd * sc.z + sh.z;
    o.w = bx.w + (v.w - mean) * rstd * sc.w + sh.w;
    ((float4*)(out + (size_t)t * DMODEL))[tid] = o;
    if (HOUT) {
        size_t oo = (size_t)t * DMODEL + tid * 4;
        *(uint2*)(oh + oo) = make_uint2(packh(o.x, o.y), packh(o.z, o.w));
    }
}

// ---------------------------------------------------------------------------
extern "C" void kernel_launch(void* const* d_in, const int* in_sizes, int n_in,
                              void* d_out, int out_size)
{
    (void)in_sizes; (void)n_in; (void)out_size;
    const float* x      = (const float*)d_in[0];
    const float* c      = (const float*)d_in[1];
    const float* w_qkv  = (const float*)d_in[2];
    const float* b_qkv  = (const float*)d_in[3];
    const float* w_proj = (const float*)d_in[4];
    const float* b_proj = (const float*)d_in[5];
    const float* w_fc1  = (const float*)d_in[6];
    const float* b_fc1  = (const float*)d_in[7];
    const float* w_fc2  = (const float*)d_in[8];
    const float* b_fc2  = (const float*)d_in[9];
    const float* w_mod1 = (const float*)d_in[10];
    const float* b_mod1 = (const float*)d_in[11];
    const float* w_mod2 = (const float*)d_in[12];
    const float* b_mod2 = (const float*)d_in[13];
    float* out = (float*)d_out;

    float *p_pro, *p_x1, *p_h2, *p_mod;
    fp16 *p_xw, *p_q, *p_aw, *p_x1f, *p_h;
    cudaGetSymbolAddress((void**)&p_pro, g_pro);
    cudaGetSymbolAddress((void**)&p_x1,  g_x1);
    cudaGetSymbolAddress((void**)&p_h2,  g_h2);
    cudaGetSymbolAddress((void**)&p_mod, g_mod);
    cudaGetSymbolAddress((void**)&p_xw,  g_xw);
    cudaGetSymbolAddress((void**)&p_q,   g_qkv);
    cudaGetSymbolAddress((void**)&p_aw,  g_aw);
    cudaGetSymbolAddress((void**)&p_x1f, g_x1f);
    cudaGetSymbolAddress((void**)&p_h,   g_h);

    fp16 *qw, *pw, *f1w, *f2w;
    cudaGetSymbolAddress((void**)&qw,  g_wqkv);
    cudaGetSymbolAddress((void**)&pw,  g_wproj);
    cudaGetSymbolAddress((void**)&f1w, g_wfc1);
    cudaGetSymbolAddress((void**)&f2w, g_wfc2);

    const int SMEM = 4 * 24576;   // 98304
    cudaFuncSetAttribute(gemm_mma<false,0>, cudaFuncAttributeMaxDynamicSharedMemorySize, SMEM);
    cudaFuncSetAttribute(gemm_mma<false,2>, cudaFuncAttributeMaxDynamicSharedMemorySize, SMEM);
    cudaFuncSetAttribute(gemm_mma<true,1>,  cudaFuncAttributeMaxDynamicSharedMemorySize, SMEM);
    cudaFuncSetAttribute(attn_mma, cudaFuncAttributeMaxDynamicSharedMemorySize, AT_TOTAL);

    dim3 wcb(32, 8);
    wconv_kernel<<<dim3(QKVDIM / 32, DMODEL / 32), wcb>>>(w_qkv,  qw,  DMODEL, QKVDIM);
    wconv_kernel<<<dim3(DMODEL / 32, DMODEL / 32), wcb>>>(w_proj, pw,  DMODEL, DMODEL);
    wconv_kernel<<<dim3(FFNDIM / 32, DMODEL / 32), wcb>>>(w_fc1,  f1w, DMODEL, FFNDIM);
    wconv_kernel<<<dim3(DMODEL / 32, FFNDIM / 32), wcb>>>(w_fc2,  f2w, FFNDIM, DMODEL);

    mod_kernel<<<8, 256>>>(c, w_mod1, b_mod1, w_mod2, b_mod2, p_mod);
    partition_kernel<<<L_TOK, 128>>>(x, p_xw);

    gemm_mma<false,2><<<dim3(QKVDIM / 256, L_TOK / 128), 256, SMEM>>>(
        p_xw, qw, b_qkv, nullptr, p_q, L_TOK, QKVDIM, DMODEL);
    attn_mma<<<NWIN * NHEAD, 288, AT_TOTAL>>>(p_q, p_aw);
    gemm_mma<false,0><<<dim3(DMODEL / 256, L_TOK / 128), 256, SMEM>>>(
        p_aw, pw, b_proj, p_pro, nullptr, L_TOK, DMODEL, DMODEL);
    adaln_kernel<true,true><<<L_TOK, 128>>>(x, p_pro, p_mod, p_mod + 512, p_x1, p_x1f);
    gemm_mma<true,1><<<dim3(FFNDIM / 256, L_TOK / 128), 256, SMEM>>>(
        p_x1f, f1w, b_fc1, nullptr, p_h, L_TOK, FFNDIM, DMODEL);
    gemm_mma<false,0><<<dim3(DMODEL / 256, L_TOK / 128), 256, SMEM>>>(
        p_h, f2w, b_fc2, p_h2, nullptr, L_TOK, DMODEL, FFNDIM);
    adaln_kernel<false,false><<<L_TOK, 128>>>(p_x1, p_h2, p_mod + 1024, p_mod + 1536,
                                              out, nullptr);
}

// round 15
// speedup vs baseline: 1.2249x; 1.2021x over previous
#include <cuda_runtime.h>
#include <cuda_fp16.h>
#include <math.h>
#include <stdint.h>

// ---------------------------------------------------------------------------
// Swin3D block, fp16 mma.sync. R15 = R9 structure (128x128 GEMM tile, 64x32
// warp tile, 2 blocks/SM) + mainloop reorder: cp.async issue moved before
// compute, second __syncthreads removed (ring distance 3 of 4 makes it safe).
// R11 lesson: keep BM=128 weight amortization. R14 lesson: stay within the
// 2-blocks/SM register budget.
// ---------------------------------------------------------------------------

#define L_TOK   36864
#define DMODEL  512
#define QKVDIM  1536
#define FFNDIM  2048
#define NWIN    256
#define WTOK    144
#define NHEAD   16
#define HDIM    32

typedef __half fp16;

// ---------------- scratch ---------------------------------------------------
__device__ fp16  g_xw  [L_TOK * DMODEL];
__device__ fp16  g_qkv [L_TOK * QKVDIM];   // attention-tile layout
__device__ fp16  g_aw  [L_TOK * DMODEL];
__device__ float g_pro [L_TOK * DMODEL];
__device__ float g_x1  [L_TOK * DMODEL];
__device__ fp16  g_x1f [L_TOK * DMODEL];
__device__ fp16  g_h   [L_TOK * FFNDIM];
__device__ float g_h2  [L_TOK * DMODEL];
__device__ float g_mod [2048];

__device__ fp16 g_wqkv [QKVDIM * DMODEL];
__device__ fp16 g_wproj[DMODEL * DMODEL];
__device__ fp16 g_wfc1 [FFNDIM * DMODEL];
__device__ fp16 g_wfc2 [DMODEL * FFNDIM];

#define TILE_BYTES 9216

// ---------------- helpers ---------------------------------------------------
__device__ __forceinline__ uint32_t smem_u32(const void* p) {
    uint32_t a;
    asm("{ .reg .u64 t; cvta.to.shared.u64 t, %1; cvt.u32.u64 %0, t; }" : "=r"(a) : "l"(p));
    return a;
}
__device__ __forceinline__ uint32_t packh(float a, float b) {
    uint32_t r;
    asm("cvt.rn.f16x2.f32 %0, %1, %2;" : "=r"(r) : "f"(b), "f"(a));
    return r;
}
__device__ __forceinline__ void cpa16(uint32_t dst, const void* src) {
    asm volatile("cp.async.cg.shared.global [%0], [%1], 16;" :: "r"(dst), "l"(src) : "memory");
}
__device__ __forceinline__ void cp_commit() {
    asm volatile("cp.async.commit_group;" ::: "memory");
}
template<int N>
__device__ __forceinline__ void cp_wait() {
    asm volatile("cp.async.wait_group %0;" :: "n"(N) : "memory");
}
__device__ __forceinline__ void ldm4(uint32_t* r, uint32_t addr) {
    asm volatile("ldmatrix.sync.aligned.m8n8.x4.shared.b16 {%0,%1,%2,%3}, [%4];"
                 : "=r"(r[0]), "=r"(r[1]), "=r"(r[2]), "=r"(r[3]) : "r"(addr));
}
__device__ __forceinline__ void ldm4t(uint32_t* r, uint32_t addr) {
    asm volatile("ldmatrix.sync.aligned.m8n8.x4.trans.shared.b16 {%0,%1,%2,%3}, [%4];"
                 : "=r"(r[0]), "=r"(r[1]), "=r"(r[2]), "=r"(r[3]) : "r"(addr));
}
__device__ __forceinline__ void mma16816(float* d, const uint32_t* a,
                                         uint32_t b0, uint32_t b1) {
    asm volatile(
        "mma.sync.aligned.m16n8k16.row.col.f32.f16.f16.f32 "
        "{%0,%1,%2,%3},{%4,%5,%6,%7},{%8,%9},{%0,%1,%2,%3};"
        : "+f"(d[0]), "+f"(d[1]), "+f"(d[2]), "+f"(d[3])
        : "r"(a[0]), "r"(a[1]), "r"(a[2]), "r"(a[3]), "r"(b0), "r"(b1));
}
__device__ __forceinline__ uint32_t tsw(int n, int d) {
    return (uint32_t)(n * 64 + (((d >> 3) ^ (n & 3)) << 4) + (d & 7) * 2);
}
__device__ __forceinline__ int winrow_to_tok(int row) {
    int win = row / WTOK, n = row % WTOK;
    int wb = win & 7, hb = (win >> 3) & 15, cb = win >> 7;
    int i = n / 72, rem = n % 72, j = rem / 12, k = rem % 12;
    int cs = cb * 2 + i, hs = hb * 6 + j, ws = wb * 12 + k;
    int c0 = (cs + 1) & 3;
    int h0 = hs + 3;  if (h0 >= 96) h0 -= 96;
    int w0 = ws + 6;  if (w0 >= 96) w0 -= 96;
    return (c0 * 96 + h0) * 96 + w0;
}

// ---------------- weight transpose + fp16 ------------------------------------
__global__ void wconv_kernel(const float* __restrict__ w,
                             fp16* __restrict__ oh, int K, int N)
{
    __shared__ float t[32][33];
    int n0 = blockIdx.x * 32, k0 = blockIdx.y * 32;
    int tx = threadIdx.x, ty = threadIdx.y;
    for (int i = ty; i < 32; i += 8)
        t[i][tx] = w[(size_t)(k0 + i) * N + n0 + tx];
    __syncthreads();
    for (int i = ty; i < 32; i += 8)
        oh[(size_t)(n0 + i) * K + k0 + tx] = __float2half(t[tx][i]);
}

// ---------------- mma.sync fp16 GEMM (128x128 tile, 4-stage ring) ------------
// OUTMODE: 0 = fp32 Cf, 1 = fp16 Ch, 2 = qkv attention tiles
#define GST 16384u
#define GOB 8192u

template<bool GELU, int OUTMODE>
__global__ __launch_bounds__(256)
void gemm_mma(const fp16* __restrict__ A, const fp16* __restrict__ B,
              const float* __restrict__ bias,
              float* __restrict__ Cf, fp16* __restrict__ Ch,
              int M, int N, int K)
{
    extern __shared__ char smc[];
    uint32_t sb = smem_u32(smc);
    int tid = threadIdx.x, wid = tid >> 5, lane = tid & 31;
    int wm = wid & 1, wn = wid >> 1;            // warp tile 64x32
    int bm = blockIdx.y * 128, bn = blockIdx.x * 128;

    int id0 = tid * 2;
    int row = id0 >> 2, c0 = id0 & 3;
    uint32_t doff[2]; int soff[2];
    #pragma unroll
    for (int l = 0; l < 2; l++) {
        int c = c0 + l;
        doff[l] = (uint32_t)(row * 64 + ((c ^ (row & 3)) << 4));
        soff[l] = c * 8;
    }
    const fp16* pA = A + (size_t)(bm + row) * K;
    const fp16* pB = B + (size_t)(bn + row) * K;

    float acc[4][4][4];
    #pragma unroll
    for (int i = 0; i < 4; i++)
        #pragma unroll
        for (int j = 0; j < 4; j++)
            #pragma unroll
            for (int q = 0; q < 4; q++) acc[i][j][q] = 0.0f;

    int NC = K >> 5;
    #pragma unroll
    for (int s = 0; s < 3; s++) {
        if (s < NC) {
            uint32_t base = sb + s * GST;
            int kof = s * 32;
            #pragma unroll
            for (int l = 0; l < 2; l++) {
                cpa16(base + doff[l],       pA + kof + soff[l]);
                cpa16(base + GOB + doff[l], pB + kof + soff[l]);
            }
        }
        cp_commit();
    }

    int arow = wm * 64 + (lane & 15);
    int akh  = lane >> 4;
    int brow = wn * 32 + (lane & 7) + ((lane >> 4) & 1) * 8;
    int bkh  = (lane >> 3) & 1;

    for (int kc = 0; kc < NC; kc++) {
        cp_wait<2>();
        __syncthreads();

        // issue next stage BEFORE compute: stage (kc+3)&3 == (kc-1)&3, whose
        // reads completed before this iteration's barrier. Overlaps LDG issue
        // with the MMA phase and removes the trailing __syncthreads.
        int kn = kc + 3;
        if (kn < NC) {
            uint32_t nbase = sb + (kn & 3) * GST;
            int kof = kn * 32;
            #pragma unroll
            for (int l = 0; l < 2; l++) {
                cpa16(nbase + doff[l],       pA + kof + soff[l]);
                cpa16(nbase + GOB + doff[l], pB + kof + soff[l]);
            }
        }
        cp_commit();

        uint32_t base = sb + (kc & 3) * GST;
        #pragma unroll
        for (int ks = 0; ks < 2; ks++) {
            uint32_t af[4][4], bfr[2][4];
            #pragma unroll
            for (int ma = 0; ma < 4; ma++) {
                int r = arow + ma * 16;
                int c = ks * 2 + akh;
                ldm4(af[ma], base + (uint32_t)(r * 64 + ((c ^ (r & 3)) << 4)));
            }
            #pragma unroll
            for (int p = 0; p < 2; p++) {
                int r = brow + p * 16;
                int c = ks * 2 + bkh;
                ldm4(bfr[p], base + GOB + (uint32_t)(r * 64 + ((c ^ (r & 3)) << 4)));
            }
            #pragma unroll
            for (int ma = 0; ma < 4; ma++)
                #pragma unroll
                for (int na = 0; na < 4; na++)
                    mma16816(acc[ma][na], af[ma],
                             bfr[na >> 1][(na & 1) * 2],
                             bfr[na >> 1][(na & 1) * 2 + 1]);
        }
    }

    int l4 = lane >> 2, l2 = (lane & 3) * 2;
    #pragma unroll
    for (int ma = 0; ma < 4; ma++) {
        int grow0 = bm + wm * 64 + ma * 16 + l4;
        #pragma unroll
        for (int na = 0; na < 4; na++) {
            int gcol = bn + wn * 32 + na * 8 + l2;
            float b0 = __ldg(bias + gcol), b1 = __ldg(bias + gcol + 1);
            float v[4];
            v[0] = acc[ma][na][0] + b0;  v[1] = acc[ma][na][1] + b1;
            v[2] = acc[ma][na][2] + b0;  v[3] = acc[ma][na][3] + b1;
            if (GELU) {
                #pragma unroll
                for (int q = 0; q < 4; q++)
                    v[q] = 0.5f * v[q] * (1.0f + erff(v[q] * 0.70710678118654752f));
            }
            #pragma unroll
            for (int half = 0; half < 2; half++) {
                int grow = grow0 + half * 8;
                float va = v[half * 2], vb = v[half * 2 + 1];
                if (OUTMODE == 2) {
                    int part = gcol >> 9, rem = gcol & 511;
                    int head = rem >> 5, d = rem & 31;
                    int win = grow / 144, n = grow - win * 144;
                    size_t tb = ((size_t)part * NWIN * NHEAD + win * NHEAD + head) * TILE_BYTES;
                    *(uint32_t*)((char*)Ch + tb + tsw(n, d)) = packh(va, vb);
                } else if (OUTMODE == 1) {
                    *(uint32_t*)(Ch + (size_t)grow * N + gcol) = packh(va, vb);
                } else {
                    float2 st; st.x = va; st.y = vb;
                    *(float2*)(Cf + (size_t)grow * N + gcol) = st;
                }
            }
        }
    }
}

// ---------------- mod GEMV ---------------------------------------------------
__global__ void mod_kernel(const float* __restrict__ c,
                           const float* __restrict__ w1, const float* __restrict__ b1,
                           const float* __restrict__ w2, const float* __restrict__ b2,
                           float* __restrict__ gmod)
{
    __shared__ float sc[512];
    int tid = threadIdx.x;
    for (int i = tid; i < 512; i += 256) {
        float v = c[i];
        sc[i] = v / (1.0f + __expf(-v));
    }
    __syncthreads();
    int o = blockIdx.x * 256 + tid;
    const float* w; const float* b; int col;
    if (o < 1024) { w = w1; b = b1; col = o; }
    else          { w = w2; b = b2; col = o - 1024; }
    float acc = b[col];
    for (int k = 0; k < 512; k++)
        acc += sc[k] * w[k * 1024 + col];
    gmod[o] = acc;
}

// ---------------- shift + window partition -> fp16 ---------------------------
__global__ void partition_kernel(const float* __restrict__ x, fp16* __restrict__ xw)
{
    int row = blockIdx.x;
    int tid = threadIdx.x;
    size_t src = (size_t)winrow_to_tok(row) * DMODEL;
    float4 f = ((const float4*)(x + src))[tid];
    size_t o = (size_t)row * DMODEL + tid * 4;
    *(uint2*)(xw + o) = make_uint2(packh(f.x, f.y), packh(f.z, f.w));
}

// ---------------- windowed attention -----------------------------------------
#define AT_Q   0u
#define AT_K   9216u
#define AT_V   18432u
#define AT_LBL 27648u
#define AT_TOTAL 28224u

__global__ __launch_bounds__(288)
void attn_mma(const fp16* __restrict__ qkv, fp16* __restrict__ aw)
{
    extern __shared__ char sm[];
    uint32_t sb = smem_u32(sm);
    int tid = threadIdx.x, warp = tid >> 5, lane = tid & 31;
    int bid = blockIdx.x;
    int win = bid >> 4, head = bid & 15;
    int wb = win & 7, hb = (win >> 3) & 15, cb = win >> 7;
    int* lbls = (int*)(sm + AT_LBL);

    {
        size_t t0 = ((size_t)win * NHEAD + head) * TILE_BYTES;
        size_t stp = (size_t)NWIN * NHEAD * TILE_BYTES;
        const char* p = (const char*)qkv;
        #pragma unroll
        for (int it = 0; it < 2; it++) {
            uint32_t off = (uint32_t)((it * 288 + tid) * 16);
            cpa16(sb + AT_Q + off, p + t0 + off);
            cpa16(sb + AT_K + off, p + t0 + stp + off);
            cpa16(sb + AT_V + off, p + t0 + 2 * stp + off);
        }
        cp_commit();
    }
    for (int n = tid; n < WTOK; n += 288) {
        int i = n / 72, rem = n % 72, j = rem / 12, k = rem % 12;
        int cs = cb * 2 + i, hs = hb * 6 + j, ws = wb * 12 + k;
        int lc = cs < 2 ? 0 : (cs < 3 ? 1 : 2);
        int lh = hs < 90 ? 0 : (hs < 93 ? 1 : 2);
        int lw = ws < 84 ? 0 : (ws < 90 ? 1 : 2);
        lbls[n] = lc * 9 + lh * 3 + lw;
    }
    cp_wait<0>();
    __syncthreads();

    int R = warp * 16;

    uint32_t qf[2][4];
    #pragma unroll
    for (int t = 0; t < 2; t++) {
        int r = R + (lane & 15);
        int c = t * 2 + (lane >> 4);
        ldm4(qf[t], sb + AT_Q + (uint32_t)(r * 64 + ((c ^ (r & 3)) << 4)));
    }

    float acc[18][4];
    #pragma unroll
    for (int nt = 0; nt < 18; nt++)
        #pragma unroll
        for (int q = 0; q < 4; q++) acc[nt][q] = 0.0f;

    #pragma unroll
    for (int t = 0; t < 2; t++) {
        #pragma unroll
        for (int jt = 0; jt < 9; jt++) {
            int r = jt * 16 + (lane & 7) + ((lane >> 4) & 1) * 8;
            int c = t * 2 + ((lane >> 3) & 1);
            uint32_t kf[4];
            ldm4(kf, sb + AT_K + (uint32_t)(r * 64 + ((c ^ (r & 3)) << 4)));
            mma16816(acc[2*jt],   qf[t], kf[0], kf[1]);
            mma16816(acc[2*jt+1], qf[t], kf[2], kf[3]);
        }
    }

    const float scale = 0.17677669529663688f;
    int r0 = R + (lane >> 2), r1 = r0 + 8;
    int li0 = lbls[r0], li1 = lbls[r1];
    float m0 = -1e30f, m1 = -1e30f;
    #pragma unroll
    for (int nt = 0; nt < 18; nt++) {
        int j0 = nt * 8 + (lane & 3) * 2;
        int lj0 = lbls[j0], lj1 = lbls[j0 + 1];
        acc[nt][0] = acc[nt][0] * scale + (lj0 == li0 ? 0.0f : -100.0f);
        acc[nt][1] = acc[nt][1] * scale + (lj1 == li0 ? 0.0f : -100.0f);
        acc[nt][2] = acc[nt][2] * scale + (lj0 == li1 ? 0.0f : -100.0f);
        acc[nt][3] = acc[nt][3] * scale + (lj1 == li1 ? 0.0f : -100.0f);
        m0 = fmaxf(m0, fmaxf(acc[nt][0], acc[nt][1]));
        m1 = fmaxf(m1, fmaxf(acc[nt][2], acc[nt][3]));
    }
    #pragma unroll
    for (int o = 1; o <= 2; o <<= 1) {
        m0 = fmaxf(m0, __shfl_xor_sync(0xffffffffu, m0, o));
        m1 = fmaxf(m1, __shfl_xor_sync(0xffffffffu, m1, o));
    }
    float s0 = 0.0f, s1 = 0.0f;
    #pragma unroll
    for (int nt = 0; nt < 18; nt++) {
        acc[nt][0] = __expf(acc[nt][0] - m0);  s0 += acc[nt][0];
        acc[nt][1] = __expf(acc[nt][1] - m0);  s0 += acc[nt][1];
        acc[nt][2] = __expf(acc[nt][2] - m1);  s1 += acc[nt][2];
        acc[nt][3] = __expf(acc[nt][3] - m1);  s1 += acc[nt][3];
    }
    #pragma unroll
    for (int o = 1; o <= 2; o <<= 1) {
        s0 += __shfl_xor_sync(0xffffffffu, s0, o);
        s1 += __shfl_xor_sync(0xffffffffu, s1, o);
    }
    float i0 = 1.0f / s0, i1 = 1.0f / s1;
    #pragma unroll
    for (int nt = 0; nt < 18; nt++) {
        acc[nt][0] *= i0; acc[nt][1] *= i0;
        acc[nt][2] *= i1; acc[nt][3] *= i1;
    }

    float pv[4][4];
    #pragma unroll
    for (int na = 0; na < 4; na++)
        #pragma unroll
        for (int q = 0; q < 4; q++) pv[na][q] = 0.0f;

    #pragma unroll
    for (int jt = 0; jt < 9; jt++) {
        uint32_t pa[4];
        pa[0] = packh(acc[2*jt][0],   acc[2*jt][1]);
        pa[1] = packh(acc[2*jt][2],   acc[2*jt][3]);
        pa[2] = packh(acc[2*jt+1][0], acc[2*jt+1][1]);
        pa[3] = packh(acc[2*jt+1][2], acc[2*jt+1][3]);
        #pragma unroll
        for (int dt = 0; dt < 2; dt++) {
            int r = jt * 16 + (lane & 15);
            int cblk = dt * 2 + (lane >> 4);
            uint32_t vf[4];
            ldm4t(vf, sb + AT_V + (uint32_t)(r * 64 + ((cblk ^ (r & 3)) << 4)));
            mma16816(pv[dt*2],   pa, vf[0], vf[1]);
            mma16816(pv[dt*2+1], pa, vf[2], vf[3]);
        }
    }

    #pragma unroll
    for (int na = 0; na < 4; na++) {
        int col = head * HDIM + na * 8 + (lane & 3) * 2;
        #pragma unroll
        for (int half = 0; half < 2; half++) {
            int grow = win * WTOK + (half ? r1 : r0);
            *(uint32_t*)(aw + (size_t)grow * DMODEL + col) =
                packh(pv[na][half * 2], pv[na][half * 2 + 1]);
        }
    }
}

// ---------------- AdaLN + residual -------------------------------------------
template<bool PERM, bool HOUT>
__global__ __launch_bounds__(128)
void adaln_kernel(const float* __restrict__ base, const float* __restrict__ src,
                  const float* __restrict__ shift, const float* __restrict__ scl,
                  float* __restrict__ out, fp16* __restrict__ oh)
{
    int t = blockIdx.x, tid = threadIdx.x;
    size_t srow;
    if (PERM) {
        int c0 = t / (96 * 96); int r = t % (96 * 96);
        int h0 = r / 96, w0 = r % 96;
        int cs = (c0 + 3) & 3;
        int hs = h0 - 3; if (hs < 0) hs += 96;
        int ws = w0 - 6; if (ws < 0) ws += 96;
        int cb = cs >> 1, i = cs & 1;
        int hb = hs / 6,  j = hs % 6;
        int wb = ws / 12, k = ws % 12;
        srow = (size_t)(((cb * 16 + hb) * 8 + wb) * WTOK + (i * 6 + j) * 12 + k);
    } else {
        srow = (size_t)t;
    }
    float4 v = ((const float4*)(src + srow * DMODEL))[tid];
    float s  = v.x + v.y + v.z + v.w;
    float sq = v.x * v.x + v.y * v.y + v.z * v.z + v.w * v.w;
    for (int o = 16; o; o >>= 1) {
        s  += __shfl_xor_sync(0xffffffffu, s,  o);
        sq += __shfl_xor_sync(0xffffffffu, sq, o);
    }
    __shared__ float rs[4], rq[4];
    int w = tid >> 5, ln = tid & 31;
    if (ln == 0) { rs[w] = s; rq[w] = sq; }
    __syncthreads();
    float S = rs[0] + rs[1] + rs[2] + rs[3];
    float Q = rq[0] + rq[1] + rq[2] + rq[3];
    float mean = S * (1.0f / 512.0f);
    float var  = Q * (1.0f / 512.0f) - mean * mean;
    float rstd = rsqrtf(var + 1e-5f);

    float4 sh = ((const float4*)shift)[tid];
    float4 sc = ((const float4*)scl)[tid];
    float4 bx = ((const float4*)(base + (size_t)t * DMODEL))[tid];
    float4 o;
    o.x = bx.x + (v.x - mean) * rstd * sc.x + sh.x;
    o.y = bx.y + (v.y - mean) * rstd * sc.y + sh.y;
    o.z = bx.z + (v.z - mean) * rstd * sc.z + sh.z;
    o.w = bx.w + (v.w - mean) * rstd * sc.w + sh.w;
    ((float4*)(out + (size_t)t * DMODEL))[tid] = o;
    if (HOUT) {
        size_t oo = (size_t)t * DMODEL + tid * 4;
        *(uint2*)(oh + oo) = make_uint2(packh(o.x, o.y), packh(o.z, o.w));
    }
}

// ---------------------------------------------------------------------------
extern "C" void kernel_launch(void* const* d_in, const int* in_sizes, int n_in,
                              void* d_out, int out_size)
{
    (void)in_sizes; (void)n_in; (void)out_size;
    const float* x      = (const float*)d_in[0];
    const float* c      = (const float*)d_in[1];
    const float* w_qkv  = (const float*)d_in[2];
    const float* b_qkv  = (const float*)d_in[3];
    const float* w_proj = (const float*)d_in[4];
    const float* b_proj = (const float*)d_in[5];
    const float* w_fc1  = (const float*)d_in[6];
    const float* b_fc1  = (const float*)d_in[7];
    const float* w_fc2  = (const float*)d_in[8];
    const float* b_fc2  = (const float*)d_in[9];
    const float* w_mod1 = (const float*)d_in[10];
    const float* b_mod1 = (const float*)d_in[11];
    const float* w_mod2 = (const float*)d_in[12];
    const float* b_mod2 = (const float*)d_in[13];
    float* out = (float*)d_out;

    float *p_pro, *p_x1, *p_h2, *p_mod;
    fp16 *p_xw, *p_q, *p_aw, *p_x1f, *p_h;
    cudaGetSymbolAddress((void**)&p_pro, g_pro);
    cudaGetSymbolAddress((void**)&p_x1,  g_x1);
    cudaGetSymbolAddress((void**)&p_h2,  g_h2);
    cudaGetSymbolAddress((void**)&p_mod, g_mod);
    cudaGetSymbolAddress((void**)&p_xw,  g_xw);
    cudaGetSymbolAddress((void**)&p_q,   g_qkv);
    cudaGetSymbolAddress((void**)&p_aw,  g_aw);
    cudaGetSymbolAddress((void**)&p_x1f, g_x1f);
    cudaGetSymbolAddress((void**)&p_h,   g_h);

    fp16 *qw, *pw, *f1w, *f2w;
    cudaGetSymbolAddress((void**)&qw,  g_wqkv);
    cudaGetSymbolAddress((void**)&pw,  g_wproj);
    cudaGetSymbolAddress((void**)&f1w, g_wfc1);
    cudaGetSymbolAddress((void**)&f2w, g_wfc2);

    const int SMEM = 65536;   // 4 stages x 16KB
    cudaFuncSetAttribute(gemm_mma<false,0>, cudaFuncAttributeMaxDynamicSharedMemorySize, SMEM);
    cudaFuncSetAttribute(gemm_mma<false,2>, cudaFuncAttributeMaxDynamicSharedMemorySize, SMEM);
    cudaFuncSetAttribute(gemm_mma<true,1>,  cudaFuncAttributeMaxDynamicSharedMemorySize, SMEM);
    cudaFuncSetAttribute(attn_mma, cudaFuncAttributeMaxDynamicSharedMemorySize, AT_TOTAL);

    dim3 wcb(32, 8);
    wconv_kernel<<<dim3(QKVDIM / 32, DMODEL / 32), wcb>>>(w_qkv,  qw,  DMODEL, QKVDIM);
    wconv_kernel<<<dim3(DMODEL / 32, DMODEL / 32), wcb>>>(w_proj, pw,  DMODEL, DMODEL);
    wconv_kernel<<<dim3(FFNDIM / 32, DMODEL / 32), wcb>>>(w_fc1,  f1w, DMODEL, FFNDIM);
    wconv_kernel<<<dim3(DMODEL / 32, FFNDIM / 32), wcb>>>(w_fc2,  f2w, FFNDIM, DMODEL);

    mod_kernel<<<8, 256>>>(c, w_mod1, b_mod1, w_mod2, b_mod2, p_mod);
    partition_kernel<<<L_TOK, 128>>>(x, p_xw);

    gemm_mma<false,2><<<dim3(QKVDIM / 128, L_TOK / 128), 256, SMEM>>>(
        p_xw, qw, b_qkv, nullptr, p_q, L_TOK, QKVDIM, DMODEL);
    attn_mma<<<NWIN * NHEAD, 288, AT_TOTAL>>>(p_q, p_aw);
    gemm_mma<false,0><<<dim3(DMODEL / 128, L_TOK / 128), 256, SMEM>>>(
        p_aw, pw, b_proj, p_pro, nullptr, L_TOK, DMODEL, DMODEL);
    adaln_kernel<true,true><<<L_TOK, 128>>>(x, p_pro, p_mod, p_mod + 512, p_x1, p_x1f);
    gemm_mma<true,1><<<dim3(FFNDIM / 128, L_TOK / 128), 256, SMEM>>>(
        p_x1f, f1w, b_fc1, nullptr, p_h, L_TOK, FFNDIM, DMODEL);
    gemm_mma<false,0><<<dim3(DMODEL / 128, L_TOK / 128), 256, SMEM>>>(
        p_h, f2w, b_fc2, p_h2, nullptr, L_TOK, DMODEL, FFNDIM);
    adaln_kernel<false,false><<<L_TOK, 128>>>(p_x1, p_h2, p_mod + 1024, p_mod + 1536,
                                              out, nullptr);
}

// round 17
// speedup vs baseline: 1.2266x; 1.0014x over previous
#include <cuda_runtime.h>
#include <cuda_fp16.h>
#include <math.h>
#include <stdint.h>

// ---------------------------------------------------------------------------
// Swin3D block, fp16 mma.sync. R15 = R9 structure (128x128 GEMM tile, 64x32
// warp tile, 2 blocks/SM) + mainloop reorder: cp.async issue moved before
// compute, second __syncthreads removed (ring distance 3 of 4 makes it safe).
// R11 lesson: keep BM=128 weight amortization. R14 lesson: stay within the
// 2-blocks/SM register budget.
// ---------------------------------------------------------------------------

#define L_TOK   36864
#define DMODEL  512
#define QKVDIM  1536
#define FFNDIM  2048
#define NWIN    256
#define WTOK    144
#define NHEAD   16
#define HDIM    32

typedef __half fp16;

// ---------------- scratch ---------------------------------------------------
__device__ fp16  g_xw  [L_TOK * DMODEL];
__device__ fp16  g_qkv [L_TOK * QKVDIM];   // attention-tile layout
__device__ fp16  g_aw  [L_TOK * DMODEL];
__device__ float g_pro [L_TOK * DMODEL];
__device__ float g_x1  [L_TOK * DMODEL];
__device__ fp16  g_x1f [L_TOK * DMODEL];
__device__ fp16  g_h   [L_TOK * FFNDIM];
__device__ float g_h2  [L_TOK * DMODEL];
__device__ float g_mod [2048];

__device__ fp16 g_wqkv [QKVDIM * DMODEL];
__device__ fp16 g_wproj[DMODEL * DMODEL];
__device__ fp16 g_wfc1 [FFNDIM * DMODEL];
__device__ fp16 g_wfc2 [DMODEL * FFNDIM];

#define TILE_BYTES 9216

// ---------------- helpers ---------------------------------------------------
__device__ __forceinline__ uint32_t smem_u32(const void* p) {
    uint32_t a;
    asm("{ .reg .u64 t; cvta.to.shared.u64 t, %1; cvt.u32.u64 %0, t; }" : "=r"(a) : "l"(p));
    return a;
}
__device__ __forceinline__ uint32_t packh(float a, float b) {
    uint32_t r;
    asm("cvt.rn.f16x2.f32 %0, %1, %2;" : "=r"(r) : "f"(b), "f"(a));
    return r;
}
__device__ __forceinline__ void cpa16(uint32_t dst, const void* src) {
    asm volatile("cp.async.cg.shared.global [%0], [%1], 16;" :: "r"(dst), "l"(src) : "memory");
}
__device__ __forceinline__ void cp_commit() {
    asm volatile("cp.async.commit_group;" ::: "memory");
}
template<int N>
__device__ __forceinline__ void cp_wait() {
    asm volatile("cp.async.wait_group %0;" :: "n"(N) : "memory");
}
__device__ __forceinline__ void ldm4(uint32_t* r, uint32_t addr) {
    asm volatile("ldmatrix.sync.aligned.m8n8.x4.shared.b16 {%0,%1,%2,%3}, [%4];"
                 : "=r"(r[0]), "=r"(r[1]), "=r"(r[2]), "=r"(r[3]) : "r"(addr));
}
__device__ __forceinline__ void ldm4t(uint32_t* r, uint32_t addr) {
    asm volatile("ldmatrix.sync.aligned.m8n8.x4.trans.shared.b16 {%0,%1,%2,%3}, [%4];"
                 : "=r"(r[0]), "=r"(r[1]), "=r"(r[2]), "=r"(r[3]) : "r"(addr));
}
__device__ __forceinline__ void mma16816(float* d, const uint32_t* a,
                                         uint32_t b0, uint32_t b1) {
    asm volatile(
        "mma.sync.aligned.m16n8k16.row.col.f32.f16.f16.f32 "
        "{%0,%1,%2,%3},{%4,%5,%6,%7},{%8,%9},{%0,%1,%2,%3};"
        : "+f"(d[0]), "+f"(d[1]), "+f"(d[2]), "+f"(d[3])
        : "r"(a[0]), "r"(a[1]), "r"(a[2]), "r"(a[3]), "r"(b0), "r"(b1));
}
__device__ __forceinline__ uint32_t tsw(int n, int d) {
    return (uint32_t)(n * 64 + (((d >> 3) ^ (n & 3)) << 4) + (d & 7) * 2);
}
__device__ __forceinline__ int winrow_to_tok(int row) {
    int win = row / WTOK, n = row % WTOK;
    int wb = win & 7, hb = (win >> 3) & 15, cb = win >> 7;
    int i = n / 72, rem = n % 72, j = rem / 12, k = rem % 12;
    int cs = cb * 2 + i, hs = hb * 6 + j, ws = wb * 12 + k;
    int c0 = (cs + 1) & 3;
    int h0 = hs + 3;  if (h0 >= 96) h0 -= 96;
    int w0 = ws + 6;  if (w0 >= 96) w0 -= 96;
    return (c0 * 96 + h0) * 96 + w0;
}

// ---------------- weight transpose + fp16 ------------------------------------
__global__ void wconv_kernel(const float* __restrict__ w,
                             fp16* __restrict__ oh, int K, int N)
{
    __shared__ float t[32][33];
    int n0 = blockIdx.x * 32, k0 = blockIdx.y * 32;
    int tx = threadIdx.x, ty = threadIdx.y;
    for (int i = ty; i < 32; i += 8)
        t[i][tx] = w[(size_t)(k0 + i) * N + n0 + tx];
    __syncthreads();
    for (int i = ty; i < 32; i += 8)
        oh[(size_t)(n0 + i) * K + k0 + tx] = __float2half(t[tx][i]);
}

// ---------------- mma.sync fp16 GEMM (128x128 tile, 4-stage ring) ------------
// OUTMODE: 0 = fp32 Cf, 1 = fp16 Ch, 2 = qkv attention tiles
#define GST 16384u
#define GOB 8192u

template<bool GELU, int OUTMODE>
__global__ __launch_bounds__(256)
void gemm_mma(const fp16* __restrict__ A, const fp16* __restrict__ B,
              const float* __restrict__ bias,
              float* __restrict__ Cf, fp16* __restrict__ Ch,
              int M, int N, int K)
{
    extern __shared__ char smc[];
    uint32_t sb = smem_u32(smc);
    int tid = threadIdx.x, wid = tid >> 5, lane = tid & 31;
    int wm = wid & 1, wn = wid >> 1;            // warp tile 64x32
    int bm = blockIdx.y * 128, bn = blockIdx.x * 128;

    int id0 = tid * 2;
    int row = id0 >> 2, c0 = id0 & 3;
    uint32_t doff[2]; int soff[2];
    #pragma unroll
    for (int l = 0; l < 2; l++) {
        int c = c0 + l;
        doff[l] = (uint32_t)(row * 64 + ((c ^ (row & 3)) << 4));
        soff[l] = c * 8;
    }
    const fp16* pA = A + (size_t)(bm + row) * K;
    const fp16* pB = B + (size_t)(bn + row) * K;

    float acc[4][4][4];
    #pragma unroll
    for (int i = 0; i < 4; i++)
        #pragma unroll
        for (int j = 0; j < 4; j++)
            #pragma unroll
            for (int q = 0; q < 4; q++) acc[i][j][q] = 0.0f;

    int NC = K >> 5;
    #pragma unroll
    for (int s = 0; s < 3; s++) {
        if (s < NC) {
            uint32_t base = sb + s * GST;
            int kof = s * 32;
            #pragma unroll
            for (int l = 0; l < 2; l++) {
                cpa16(base + doff[l],       pA + kof + soff[l]);
                cpa16(base + GOB + doff[l], pB + kof + soff[l]);
            }
        }
        cp_commit();
    }

    int arow = wm * 64 + (lane & 15);
    int akh  = lane >> 4;
    int brow = wn * 32 + (lane & 7) + ((lane >> 4) & 1) * 8;
    int bkh  = (lane >> 3) & 1;

    for (int kc = 0; kc < NC; kc++) {
        cp_wait<2>();
        __syncthreads();

        // issue next stage BEFORE compute: stage (kc+3)&3 == (kc-1)&3, whose
        // reads completed before this iteration's barrier. Overlaps LDG issue
        // with the MMA phase and removes the trailing __syncthreads.
        int kn = kc + 3;
        if (kn < NC) {
            uint32_t nbase = sb + (kn & 3) * GST;
            int kof = kn * 32;
            #pragma unroll
            for (int l = 0; l < 2; l++) {
                cpa16(nbase + doff[l],       pA + kof + soff[l]);
                cpa16(nbase + GOB + doff[l], pB + kof + soff[l]);
            }
        }
        cp_commit();

        uint32_t base = sb + (kc & 3) * GST;
        #pragma unroll
        for (int ks = 0; ks < 2; ks++) {
            uint32_t af[4][4], bfr[2][4];
            #pragma unroll
            for (int ma = 0; ma < 4; ma++) {
                int r = arow + ma * 16;
                int c = ks * 2 + akh;
                ldm4(af[ma], base + (uint32_t)(r * 64 + ((c ^ (r & 3)) << 4)));
            }
            #pragma unroll
            for (int p = 0; p < 2; p++) {
                int r = brow + p * 16;
                int c = ks * 2 + bkh;
                ldm4(bfr[p], base + GOB + (uint32_t)(r * 64 + ((c ^ (r & 3)) << 4)));
            }
            #pragma unroll
            for (int ma = 0; ma < 4; ma++)
                #pragma unroll
                for (int na = 0; na < 4; na++)
                    mma16816(acc[ma][na], af[ma],
                             bfr[na >> 1][(na & 1) * 2],
                             bfr[na >> 1][(na & 1) * 2 + 1]);
        }
    }

    int l4 = lane >> 2, l2 = (lane & 3) * 2;
    #pragma unroll
    for (int ma = 0; ma < 4; ma++) {
        int grow0 = bm + wm * 64 + ma * 16 + l4;
        #pragma unroll
        for (int na = 0; na < 4; na++) {
            int gcol = bn + wn * 32 + na * 8 + l2;
            float b0 = __ldg(bias + gcol), b1 = __ldg(bias + gcol + 1);
            float v[4];
            v[0] = acc[ma][na][0] + b0;  v[1] = acc[ma][na][1] + b1;
            v[2] = acc[ma][na][2] + b0;  v[3] = acc[ma][na][3] + b1;
            if (GELU) {
                #pragma unroll
                for (int q = 0; q < 4; q++)
                    v[q] = 0.5f * v[q] * (1.0f + erff(v[q] * 0.70710678118654752f));
            }
            #pragma unroll
            for (int half = 0; half < 2; half++) {
                int grow = grow0 + half * 8;
                float va = v[half * 2], vb = v[half * 2 + 1];
                if (OUTMODE == 2) {
                    int part = gcol >> 9, rem = gcol & 511;
                    int head = rem >> 5, d = rem & 31;
                    int win = grow / 144, n = grow - win * 144;
                    size_t tb = ((size_t)part * NWIN * NHEAD + win * NHEAD + head) * TILE_BYTES;
                    *(uint32_t*)((char*)Ch + tb + tsw(n, d)) = packh(va, vb);
                } else if (OUTMODE == 1) {
                    *(uint32_t*)(Ch + (size_t)grow * N + gcol) = packh(va, vb);
                } else {
                    float2 st; st.x = va; st.y = vb;
                    *(float2*)(Cf + (size_t)grow * N + gcol) = st;
                }
            }
        }
    }
}

// ---------------- mod GEMV ---------------------------------------------------
__global__ void mod_kernel(const float* __restrict__ c,
                           const float* __restrict__ w1, const float* __restrict__ b1,
                           const float* __restrict__ w2, const float* __restrict__ b2,
                           float* __restrict__ gmod)
{
    __shared__ float sc[512];
    int tid = threadIdx.x;
    for (int i = tid; i < 512; i += 256) {
        float v = c[i];
        sc[i] = v / (1.0f + __expf(-v));
    }
    __syncthreads();
    int o = blockIdx.x * 256 + tid;
    const float* w; const float* b; int col;
    if (o < 1024) { w = w1; b = b1; col = o; }
    else          { w = w2; b = b2; col = o - 1024; }
    float acc = b[col];
    for (int k = 0; k < 512; k++)
        acc += sc[k] * w[k * 1024 + col];
    gmod[o] = acc;
}

// ---------------- shift + window partition -> fp16 ---------------------------
__global__ void partition_kernel(const float* __restrict__ x, fp16* __restrict__ xw)
{
    int row = blockIdx.x;
    int tid = threadIdx.x;
    size_t src = (size_t)winrow_to_tok(row) * DMODEL;
    float4 f = ((const float4*)(x + src))[tid];
    size_t o = (size_t)row * DMODEL + tid * 4;
    *(uint2*)(xw + o) = make_uint2(packh(f.x, f.y), packh(f.z, f.w));
}

// ---------------- windowed attention -----------------------------------------
#define AT_Q   0u
#define AT_K   9216u
#define AT_V   18432u
#define AT_LBL 27648u
#define AT_TOTAL 28224u

__global__ __launch_bounds__(288)
void attn_mma(const fp16* __restrict__ qkv, fp16* __restrict__ aw)
{
    extern __shared__ char sm[];
    uint32_t sb = smem_u32(sm);
    int tid = threadIdx.x, warp = tid >> 5, lane = tid & 31;
    int bid = blockIdx.x;
    int win = bid >> 4, head = bid & 15;
    int wb = win & 7, hb = (win >> 3) & 15, cb = win >> 7;
    int* lbls = (int*)(sm + AT_LBL);

    {
        size_t t0 = ((size_t)win * NHEAD + head) * TILE_BYTES;
        size_t stp = (size_t)NWIN * NHEAD * TILE_BYTES;
        const char* p = (const char*)qkv;
        #pragma unroll
        for (int it = 0; it < 2; it++) {
            uint32_t off = (uint32_t)((it * 288 + tid) * 16);
            cpa16(sb + AT_Q + off, p + t0 + off);
            cpa16(sb + AT_K + off, p + t0 + stp + off);
            cpa16(sb + AT_V + off, p + t0 + 2 * stp + off);
        }
        cp_commit();
    }
    for (int n = tid; n < WTOK; n += 288) {
        int i = n / 72, rem = n % 72, j = rem / 12, k = rem % 12;
        int cs = cb * 2 + i, hs = hb * 6 + j, ws = wb * 12 + k;
        int lc = cs < 2 ? 0 : (cs < 3 ? 1 : 2);
        int lh = hs < 90 ? 0 : (hs < 93 ? 1 : 2);
        int lw = ws < 84 ? 0 : (ws < 90 ? 1 : 2);
        lbls[n] = lc * 9 + lh * 3 + lw;
    }
    cp_wait<0>();
    __syncthreads();

    int R = warp * 16;

    uint32_t qf[2][4];
    #pragma unroll
    for (int t = 0; t < 2; t++) {
        int r = R + (lane & 15);
        int c = t * 2 + (lane >> 4);
        ldm4(qf[t], sb + AT_Q + (uint32_t)(r * 64 + ((c ^ (r & 3)) << 4)));
    }

    float acc[18][4];
    #pragma unroll
    for (int nt = 0; nt < 18; nt++)
        #pragma unroll
        for (int q = 0; q < 4; q++) acc[nt][q] = 0.0f;

    #pragma unroll
    for (int t = 0; t < 2; t++) {
        #pragma unroll
        for (int jt = 0; jt < 9; jt++) {
            int r = jt * 16 + (lane & 7) + ((lane >> 4) & 1) * 8;
            int c = t * 2 + ((lane >> 3) & 1);
            uint32_t kf[4];
            ldm4(kf, sb + AT_K + (uint32_t)(r * 64 + ((c ^ (r & 3)) << 4)));
            mma16816(acc[2*jt],   qf[t], kf[0], kf[1]);
            mma16816(acc[2*jt+1], qf[t], kf[2], kf[3]);
        }
    }

    const float scale = 0.17677669529663688f;
    int r0 = R + (lane >> 2), r1 = r0 + 8;
    int li0 = lbls[r0], li1 = lbls[r1];
    float m0 = -1e30f, m1 = -1e30f;
    #pragma unroll
    for (int nt = 0; nt < 18; nt++) {
        int j0 = nt * 8 + (lane & 3) * 2;
        int lj0 = lbls[j0], lj1 = lbls[j0 + 1];
        acc[nt][0] = acc[nt][0] * scale + (lj0 == li0 ? 0.0f : -100.0f);
        acc[nt][1] = acc[nt][1] * scale + (lj1 == li0 ? 0.0f : -100.0f);
        acc[nt][2] = acc[nt][2] * scale + (lj0 == li1 ? 0.0f : -100.0f);
        acc[nt][3] = acc[nt][3] * scale + (lj1 == li1 ? 0.0f : -100.0f);
        m0 = fmaxf(m0, fmaxf(acc[nt][0], acc[nt][1]));
        m1 = fmaxf(m1, fmaxf(acc[nt][2], acc[nt][3]));
    }
    #pragma unroll
    for (int o = 1; o <= 2; o <<= 1) {
        m0 = fmaxf(m0, __shfl_xor_sync(0xffffffffu, m0, o));
        m1 = fmaxf(m1, __shfl_xor_sync(0xffffffffu, m1, o));
    }
    float s0 = 0.0f, s1 = 0.0f;
    #pragma unroll
    for (int nt = 0; nt < 18; nt++) {
        acc[nt][0] = __expf(acc[nt][0] - m0);  s0 += acc[nt][0];
        acc[nt][1] = __expf(acc[nt][1] - m0);  s0 += acc[nt][1];
        acc[nt][2] = __expf(acc[nt][2] - m1);  s1 += acc[nt][2];
        acc[nt][3] = __expf(acc[nt][3] - m1);  s1 += acc[nt][3];
    }
    #pragma unroll
    for (int o = 1; o <= 2; o <<= 1) {
        s0 += __shfl_xor_sync(0xffffffffu, s0, o);
        s1 += __shfl_xor_sync(0xffffffffu, s1, o);
    }
    float i0 = 1.0f / s0, i1 = 1.0f / s1;
    #pragma unroll
    for (int nt = 0; nt < 18; nt++) {
        acc[nt][0] *= i0; acc[nt][1] *= i0;
        acc[nt][2] *= i1; acc[nt][3] *= i1;
    }

    float pv[4][4];
    #pragma unroll
    for (int na = 0; na < 4; na++)
        #pragma unroll
        for (int q = 0; q < 4; q++) pv[na][q] = 0.0f;

    #pragma unroll
    for (int jt = 0; jt < 9; jt++) {
        uint32_t pa[4];
        pa[0] = packh(acc[2*jt][0],   acc[2*jt][1]);
        pa[1] = packh(acc[2*jt][2],   acc[2*jt][3]);
        pa[2] = packh(acc[2*jt+1][0], acc[2*jt+1][1]);
        pa[3] = packh(acc[2*jt+1][2], acc[2*jt+1][3]);
        #pragma unroll
        for (int dt = 0; dt < 2; dt++) {
            int r = jt * 16 + (lane & 15);
            int cblk = dt * 2 + (lane >> 4);
            uint32_t vf[4];
            ldm4t(vf, sb + AT_V + (uint32_t)(r * 64 + ((cblk ^ (r & 3)) << 4)));
            mma16816(pv[dt*2],   pa, vf[0], vf[1]);
            mma16816(pv[dt*2+1], pa, vf[2], vf[3]);
        }
    }

    #pragma unroll
    for (int na = 0; na < 4; na++) {
        int col = head * HDIM + na * 8 + (lane & 3) * 2;
        #pragma unroll
        for (int half = 0; half < 2; half++) {
            int grow = win * WTOK + (half ? r1 : r0);
            *(uint32_t*)(aw + (size_t)grow * DMODEL + col) =
                packh(pv[na][half * 2], pv[na][half * 2 + 1]);
        }
    }
}

// ---------------- AdaLN + residual -------------------------------------------
template<bool PERM, bool HOUT>
__global__ __launch_bounds__(128)
void adaln_kernel(const float* __restrict__ base, const float* __restrict__ src,
                  const float* __restrict__ shift, const float* __restrict__ scl,
                  float* __restrict__ out, fp16* __restrict__ oh)
{
    int t = blockIdx.x, tid = threadIdx.x;
    size_t srow;
    if (PERM) {
        int c0 = t / (96 * 96); int r = t % (96 * 96);
        int h0 = r / 96, w0 = r % 96;
        int cs = (c0 + 3) & 3;
        int hs = h0 - 3; if (hs < 0) hs += 96;
        int ws = w0 - 6; if (ws < 0) ws += 96;
        int cb = cs >> 1, i = cs & 1;
        int hb = hs / 6,  j = hs % 6;
        int wb = ws / 12, k = ws % 12;
        srow = (size_t)(((cb * 16 + hb) * 8 + wb) * WTOK + (i * 6 + j) * 12 + k);
    } else {
        srow = (size_t)t;
    }
    float4 v = ((const float4*)(src + srow * DMODEL))[tid];
    float s  = v.x + v.y + v.z + v.w;
    float sq = v.x * v.x + v.y * v.y + v.z * v.z + v.w * v.w;
    for (int o = 16; o; o >>= 1) {
        s  += __shfl_xor_sync(0xffffffffu, s,  o);
        sq += __shfl_xor_sync(0xffffffffu, sq, o);
    }
    __shared__ float rs[4], rq[4];
    int w = tid >> 5, ln = tid & 31;
    if (ln == 0) { rs[w] = s; rq[w] = sq; }
    __syncthreads();
    float S = rs[0] + rs[1] + rs[2] + rs[3];
    float Q = rq[0] + rq[1] + rq[2] + rq[3];
    float mean = S * (1.0f / 512.0f);
    float var  = Q * (1.0f / 512.0f) - mean * mean;
    float rstd = rsqrtf(var + 1e-5f);

    float4 sh = ((const float4*)shift)[tid];
    float4 sc = ((const float4*)scl)[tid];
    float4 bx = ((const float4*)(base + (size_t)t * DMODEL))[tid];
    float4 o;
    o.x = bx.x + (v.x - mean) * rstd * sc.x + sh.x;
    o.y = bx.y + (v.y - mean) * rstd * sc.y + sh.y;
    o.z = bx.z + (v.z - mean) * rstd * sc.z + sh.z;
    o.w = bx.w + (v.w - mean) * rstd * sc.w + sh.w;
    ((float4*)(out + (size_t)t * DMODEL))[tid] = o;
    if (HOUT) {
        size_t oo = (size_t)t * DMODEL + tid * 4;
        *(uint2*)(oh + oo) = make_uint2(packh(o.x, o.y), packh(o.z, o.w));
    }
}

// ---------------------------------------------------------------------------
extern "C" void kernel_launch(void* const* d_in, const int* in_sizes, int n_in,
                              void* d_out, int out_size)
{
    (void)in_sizes; (void)n_in; (void)out_size;
    const float* x      = (const float*)d_in[0];
    const float* c      = (const float*)d_in[1];
    const float* w_qkv  = (const float*)d_in[2];
    const float* b_qkv  = (const float*)d_in[3];
    const float* w_proj = (const float*)d_in[4];
    const float* b_proj = (const float*)d_in[5];
    const float* w_fc1  = (const float*)d_in[6];
    const float* b_fc1  = (const float*)d_in[7];
    const float* w_fc2  = (const float*)d_in[8];
    const float* b_fc2  = (const float*)d_in[9];
    const float* w_mod1 = (const float*)d_in[10];
    const float* b_mod1 = (const float*)d_in[11];
    const float* w_mod2 = (const float*)d_in[12];
    const float* b_mod2 = (const float*)d_in[13];
    float* out = (float*)d_out;

    float *p_pro, *p_x1, *p_h2, *p_mod;
    fp16 *p_xw, *p_q, *p_aw, *p_x1f, *p_h;
    cudaGetSymbolAddress((void**)&p_pro, g_pro);
    cudaGetSymbolAddress((void**)&p_x1,  g_x1);
    cudaGetSymbolAddress((void**)&p_h2,  g_h2);
    cudaGetSymbolAddress((void**)&p_mod, g_mod);
    cudaGetSymbolAddress((void**)&p_xw,  g_xw);
    cudaGetSymbolAddress((void**)&p_q,   g_qkv);
    cudaGetSymbolAddress((void**)&p_aw,  g_aw);
    cudaGetSymbolAddress((void**)&p_x1f, g_x1f);
    cudaGetSymbolAddress((void**)&p_h,   g_h);

    fp16 *qw, *pw, *f1w, *f2w;
    cudaGetSymbolAddress((void**)&qw,  g_wqkv);
    cudaGetSymbolAddress((void**)&pw,  g_wproj);
    cudaGetSymbolAddress((void**)&f1w, g_wfc1);
    cudaGetSymbolAddress((void**)&f2w, g_wfc2);

    const int SMEM = 65536;   // 4 stages x 16KB
    cudaFuncSetAttribute(gemm_mma<false,0>, cudaFuncAttributeMaxDynamicSharedMemorySize, SMEM);
    cudaFuncSetAttribute(gemm_mma<false,2>, cudaFuncAttributeMaxDynamicSharedMemorySize, SMEM);
    cudaFuncSetAttribute(gemm_mma<true,1>,  cudaFuncAttributeMaxDynamicSharedMemorySize, SMEM);
    cudaFuncSetAttribute(attn_mma, cudaFuncAttributeMaxDynamicSharedMemorySize, AT_TOTAL);

    dim3 wcb(32, 8);
    wconv_kernel<<<dim3(QKVDIM / 32, DMODEL / 32), wcb>>>(w_qkv,  qw,  DMODEL, QKVDIM);
    wconv_kernel<<<dim3(DMODEL / 32, DMODEL / 32), wcb>>>(w_proj, pw,  DMODEL, DMODEL);
    wconv_kernel<<<dim3(FFNDIM / 32, DMODEL / 32), wcb>>>(w_fc1,  f1w, DMODEL, FFNDIM);
    wconv_kernel<<<dim3(DMODEL / 32, FFNDIM / 32), wcb>>>(w_fc2,  f2w, FFNDIM, DMODEL);

    mod_kernel<<<8, 256>>>(c, w_mod1, b_mod1, w_mod2, b_mod2, p_mod);
    partition_kernel<<<L_TOK, 128>>>(x, p_xw);

    gemm_mma<false,2><<<dim3(QKVDIM / 128, L_TOK / 128), 256, SMEM>>>(
        p_xw, qw, b_qkv, nullptr, p_q, L_TOK, QKVDIM, DMODEL);
    attn_mma<<<NWIN * NHEAD, 288, AT_TOTAL>>>(p_q, p_aw);
    gemm_mma<false,0><<<dim3(DMODEL / 128, L_TOK / 128), 256, SMEM>>>(
        p_aw, pw, b_proj, p_pro, nullptr, L_TOK, DMODEL, DMODEL);
    adaln_kernel<true,true><<<L_TOK, 128>>>(x, p_pro, p_mod, p_mod + 512, p_x1, p_x1f);
    gemm_mma<true,1><<<dim3(FFNDIM / 128, L_TOK / 128), 256, SMEM>>>(
        p_x1f, f1w, b_fc1, nullptr, p_h, L_TOK, FFNDIM, DMODEL);
    gemm_mma<false,0><<<dim3(DMODEL / 128, L_TOK / 128), 256, SMEM>>>(
        p_h, f2w, b_fc2, p_h2, nullptr, L_TOK, DMODEL, FFNDIM);
    adaln_kernel<false,false><<<L_TOK, 128>>>(p_x1, p_h2, p_mod + 1024, p_mod + 1536,
                                              out, nullptr);
}